// round 5
// baseline (speedup 1.0000x reference)
#include <cuda_runtime.h>
#include <math.h>

// ---------------- problem constants ----------------
#define NBATCH 1024
#define NP     31        // patches per sequence
#define LPN    64        // patch length (graph nodes)
#define GHD    64        // gnn hidden
#define RHD    128       // rnn hidden
#define NC     11

// ---------------- device scratch (static, no allocation) ----------------
__device__ float g_aw[64 * 17];          // banded adjacency * deg_inv
__device__ float g_b1[64];               // bs1+bn1
__device__ float g_b2[64];               // bs2+bn2
__device__ float g_w1[256];              // [Ws1t(2x64) ; Wn1t(2x64)]  (d-major)
__device__ float g_Ws2t[4096];           // Ws2 transposed [d][o]
__device__ float g_Wn2t[4096];           // Wn2 transposed [d][o]
__device__ float g_b0c[512];             // bih0+bhh0
__device__ float g_b1l[512];             // bih1+bhh1
__device__ float g_Wih0t[64 * 512];      // Wih0 transposed [k][n]
__device__ float g_Wc1t[128 * 64];       // Wc1 transposed [k][o]
__device__ float g_feats[NBATCH * NP * 64];
__device__ float g_xg0[NBATCH * NP * 512];
__device__ float g_H0[2][NBATCH * RHD];  // ping-pong
__device__ float g_C0[NBATCH * RHD];
__device__ float g_H1[2][NBATCH * RHD];  // ping-pong
__device__ float g_C1[NBATCH * RHD];
__device__ float g_hid[NBATCH * 64];

__device__ __forceinline__ float sigm(float x) { return 1.0f / (1.0f + expf(-x)); }

// ---------------- prep: adjacency band, transposes, combined biases ----------------
__global__ void prep_kernel(const float* __restrict__ E,
                            const float* __restrict__ Wn1, const float* __restrict__ bn1,
                            const float* __restrict__ Ws1, const float* __restrict__ bs1,
                            const float* __restrict__ Wn2, const float* __restrict__ bn2,
                            const float* __restrict__ Ws2, const float* __restrict__ bs2,
                            const float* __restrict__ Wih0,
                            const float* __restrict__ bih0, const float* __restrict__ bhh0,
                            const float* __restrict__ bih1, const float* __restrict__ bhh1,
                            const float* __restrict__ Wc1) {
    const int tid = threadIdx.x;
    if (tid < 64) {
        float row[17];
        float deg = 0.0f;
#pragma unroll
        for (int k = 0; k < 17; k++) {
            int j = tid - 8 + k;
            float a = 0.0f;
            if (j >= 0 && j < 64 && j != tid) a = 1.0f / (1.0f + expf(-E[tid * 64 + j]));
            row[k] = a;
            deg += a;
        }
        float inv = deg > 0.0f ? 1.0f / deg : 0.0f;
#pragma unroll
        for (int k = 0; k < 17; k++) g_aw[tid * 17 + k] = row[k] * inv;
        g_b1[tid] = bs1[tid] + bn1[tid];
        g_b2[tid] = bs2[tid] + bn2[tid];
        g_w1[tid]       = Ws1[tid * 2 + 0];
        g_w1[64 + tid]  = Ws1[tid * 2 + 1];
        g_w1[128 + tid] = Wn1[tid * 2 + 0];
        g_w1[192 + tid] = Wn1[tid * 2 + 1];
    }
    for (int idx = tid; idx < 4096; idx += 256) {
        int o = idx >> 6, d = idx & 63;
        g_Ws2t[d * 64 + o] = Ws2[idx];
        g_Wn2t[d * 64 + o] = Wn2[idx];
    }
    for (int idx = tid; idx < 512; idx += 256) {
        g_b0c[idx] = bih0[idx] + bhh0[idx];
        g_b1l[idx] = bih1[idx] + bhh1[idx];
    }
    for (int idx = tid; idx < 512 * 64; idx += 256) {
        int n = idx >> 6, k = idx & 63;
        g_Wih0t[k * 512 + n] = Wih0[idx];
    }
    for (int idx = tid; idx < 64 * 128; idx += 256) {
        int o = idx >> 7, k = idx & 127;
        g_Wc1t[k * 64 + o] = Wc1[idx];
    }
}

// ---------------- zero LSTM initial state ----------------
__global__ void zero_kernel() {
    int i = blockIdx.x * blockDim.x + threadIdx.x;
    if (i < NBATCH * RHD) {
        g_H0[1][i] = 0.0f;
        g_C0[i]    = 0.0f;
        g_H1[1][i] = 0.0f;
        g_C1[i]    = 0.0f;
    }
}

// ---------------- fused GNN: 2 SAGE layers + node-sum, one CTA per (b,p) ----------------
// dynamic smem layout (floats):
//   x1[4096] n1[4096] Ws[4096] Wn[4096] aw[1088] x0[128] n0[128] w1[256] b1s[64] b2s[64] feat[64]
#define GNN_SMEM_FLOATS 18176
__global__ __launch_bounds__(256) void gnn_kernel(const float* __restrict__ I,
                                                  const float* __restrict__ Q) {
    extern __shared__ float sm[];
    float* x1   = sm;
    float* n1   = sm + 4096;
    float* Ws   = sm + 8192;
    float* Wn   = sm + 12288;
    float* aw   = sm + 16384;
    float* x0   = aw + 1088;
    float* n0   = x0 + 128;
    float* w1   = n0 + 128;
    float* b1s  = w1 + 256;
    float* b2s  = b1s + 64;
    float* feat = b2s + 64;

    const int tid = threadIdx.x;
    const int bp  = blockIdx.x;
    const int b   = bp / NP;
    const int p   = bp - b * NP;

    for (int idx = tid; idx < 4096; idx += 256) {
        Ws[idx] = g_Ws2t[idx];
        Wn[idx] = g_Wn2t[idx];
    }
    for (int idx = tid; idx < 1088; idx += 256) aw[idx] = g_aw[idx];
    if (tid < 256) { /* all threads */ }
    w1[tid] = g_w1[tid];
    if (tid < 64) {
        b1s[tid] = g_b1[tid];
        b2s[tid] = g_b2[tid];
        int pos = b * 1024 + p * 32 + tid;
        x0[tid * 2 + 0] = I[pos];
        x0[tid * 2 + 1] = Q[pos];
    }
    __syncthreads();

    // neigh0[i][d] (d=2)
    if (tid < 128) {
        int i = tid >> 1, d = tid & 1;
        float s = 0.0f;
#pragma unroll
        for (int k = 0; k < 17; k++) {
            int j = i - 8 + k;
            j = max(0, min(63, j));
            s += aw[i * 17 + k] * x0[j * 2 + d];
        }
        n0[tid] = s;
    }
    __syncthreads();

    // SAGE layer 1: x1[i][o] = relu(self + neigh + bias)
    {
        const int o = tid & 63, ig = tid >> 6;
        const float ws0 = w1[o], ws1 = w1[64 + o], wn0 = w1[128 + o], wn1 = w1[192 + o];
        const float bb = b1s[o];
#pragma unroll
        for (int ii = 0; ii < 16; ii++) {
            int i = ig * 16 + ii;
            float v = bb + x0[i * 2] * ws0 + x0[i * 2 + 1] * ws1
                         + n0[i * 2] * wn0 + n0[i * 2 + 1] * wn1;
            x1[i * 64 + o] = fmaxf(v, 0.0f);
        }
    }
    __syncthreads();

    // neigh1[i][d] over band
    {
        const int d = tid & 63, ig = tid >> 6;
#pragma unroll
        for (int ii = 0; ii < 16; ii++) {
            int i = ig * 16 + ii;
            float s = 0.0f;
#pragma unroll
            for (int k = 0; k < 17; k++) {
                int j = i - 8 + k;
                j = max(0, min(63, j));
                s += aw[i * 17 + k] * x1[j * 64 + d];
            }
            n1[i * 64 + d] = s;
        }
    }
    __syncthreads();

    // SAGE layer 2 GEMM (64x64x128) with 4x4 register tiles, then node-sum
    {
        const int i0 = (tid >> 4) * 4;
        const int o0 = (tid & 15) * 4;
        float acc[4][4] = {};
#pragma unroll 4
        for (int d = 0; d < 64; d++) {
            const float4 ws = *(const float4*)(Ws + d * 64 + o0);
            const float4 wn = *(const float4*)(Wn + d * 64 + o0);
#pragma unroll
            for (int ii = 0; ii < 4; ii++) {
                float a = x1[(i0 + ii) * 64 + d];
                float e = n1[(i0 + ii) * 64 + d];
                acc[ii][0] += a * ws.x + e * wn.x;
                acc[ii][1] += a * ws.y + e * wn.y;
                acc[ii][2] += a * ws.z + e * wn.z;
                acc[ii][3] += a * ws.w + e * wn.w;
            }
        }
        float fs[4] = {0.f, 0.f, 0.f, 0.f};
#pragma unroll
        for (int oo = 0; oo < 4; oo++) {
            float bb = b2s[o0 + oo];
#pragma unroll
            for (int ii = 0; ii < 4; ii++) fs[oo] += fmaxf(acc[ii][oo] + bb, 0.0f);
        }
        __syncthreads();  // done reading x1 — reuse it as reduction buffer
        const int ig = tid >> 4;
#pragma unroll
        for (int oo = 0; oo < 4; oo++) x1[ig * 64 + o0 + oo] = fs[oo];
    }
    __syncthreads();
    if (tid < 64) {
        float s = 0.0f;
#pragma unroll
        for (int g = 0; g < 16; g++) s += x1[g * 64 + tid];
        g_feats[bp * 64 + tid] = s;
    }
    (void)feat;
}

// ---------------- xg0 = feats @ Wih0^T + (bih0+bhh0) : [31744 x 512], K=64 ----------------
__global__ __launch_bounds__(256) void xg0_kernel() {
    __shared__ float As[64 * 64];
    __shared__ float Bs[64 * 64];
    __shared__ float bsm[64];
    const int m0 = blockIdx.x * 64;
    const int n0 = blockIdx.y * 64;
    const int tid = threadIdx.x;
    for (int idx = tid; idx < 4096; idx += 256) As[idx] = g_feats[(m0 + (idx >> 6)) * 64 + (idx & 63)];
    for (int idx = tid; idx < 4096; idx += 256) Bs[idx] = g_Wih0t[(idx >> 6) * 512 + n0 + (idx & 63)];
    if (tid < 64) bsm[tid] = g_b0c[n0 + tid];
    __syncthreads();
    const int mi0 = (tid >> 4) * 4;
    const int ni0 = (tid & 15) * 4;
    float acc[4][4] = {};
#pragma unroll 4
    for (int k = 0; k < 64; k++) {
        const float4 bv = *(const float4*)(Bs + k * 64 + ni0);
#pragma unroll
        for (int ii = 0; ii < 4; ii++) {
            float a = As[(mi0 + ii) * 64 + k];
            acc[ii][0] += a * bv.x;
            acc[ii][1] += a * bv.y;
            acc[ii][2] += a * bv.z;
            acc[ii][3] += a * bv.w;
        }
    }
#pragma unroll
    for (int ii = 0; ii < 4; ii++)
#pragma unroll
        for (int jj = 0; jj < 4; jj++)
            g_xg0[(m0 + mi0 + ii) * 512 + n0 + ni0 + jj] = acc[ii][jj] + bsm[ni0 + jj];
}

// ---------------- pipelined LSTM step: layer0(t) on blocks[0,128), layer1(t-1) on blocks[128,384) ----
// dynamic smem: 128*129 (weights, pitch 129) + 32*129 (h)  == 20640 floats for both branches
#define LSTM_SMEM_FLOATS 20640
__global__ __launch_bounds__(256) void lstm_step_kernel(int t,
                                                        const float* __restrict__ Whh0,
                                                        const float* __restrict__ Wih1,
                                                        const float* __restrict__ Whh1) {
    extern __shared__ float sm[];
    const int tid = threadIdx.x;
    const int jj = tid & 31;
    const int bg = tid >> 5;  // 0..7

    if (blockIdx.x < 128) {
        // ---- layer0, time step t ----
        if (t > 30) return;
        const int b0 = (blockIdx.x >> 2) * 32;
        const int j0 = (blockIdx.x & 3) * 32;
        float* Wsm = sm;             // [128 rows][pitch 129]
        float* hs  = sm + 128 * 129; // [32][129]
        const float* __restrict__ hprev = g_H0[(t + 1) & 1];
        for (int idx = tid; idx < 32 * 128; idx += 256) {
            int bb = idx >> 7, k = idx & 127;
            hs[bb * 129 + k] = hprev[(b0 + bb) * 128 + k];
        }
        for (int idx = tid; idx < 128 * 128; idx += 256) {
            int r = idx >> 7, k = idx & 127;
            int q = r >> 5, j = r & 31;
            Wsm[r * 129 + k] = Whh0[(q * 128 + j0 + j) * 128 + k];
        }
        __syncthreads();
        float acc[4][4] = {};
#pragma unroll 4
        for (int k = 0; k < 128; k++) {
            float w0 = Wsm[jj * 129 + k];
            float w1v = Wsm[(32 + jj) * 129 + k];
            float w2 = Wsm[(64 + jj) * 129 + k];
            float w3 = Wsm[(96 + jj) * 129 + k];
#pragma unroll
            for (int i = 0; i < 4; i++) {
                float h = hs[(bg * 4 + i) * 129 + k];
                acc[i][0] += w0 * h;
                acc[i][1] += w1v * h;
                acc[i][2] += w2 * h;
                acc[i][3] += w3 * h;
            }
        }
        const int j = j0 + jj;
#pragma unroll
        for (int i = 0; i < 4; i++) {
            int b = b0 + bg * 4 + i;
            const float* xg = g_xg0 + (b * NP + t) * 512;
            float gi = acc[i][0] + xg[j];
            float gf = acc[i][1] + xg[128 + j];
            float gg = acc[i][2] + xg[256 + j];
            float go = acc[i][3] + xg[384 + j];
            float c = g_C0[b * 128 + j];
            c = sigm(gf) * c + sigm(gi) * tanhf(gg);
            float h = sigm(go) * tanhf(c);
            g_C0[b * 128 + j] = c;
            g_H0[t & 1][b * 128 + j] = h;
        }
    } else {
        // ---- layer1, time step s = t-1 ----
        const int s = t - 1;
        if (s < 0) return;
        const int blk = blockIdx.x - 128;   // 0..255
        const int b0 = (blk >> 2) * 16;
        const int j0 = (blk & 3) * 32;
        float* Wsm = sm;
        float* h0s = sm + 128 * 129;  // [16][129]
        float* h1s = h0s + 16 * 129;  // [16][129]
        const float* __restrict__ h0in = g_H0[s & 1];
        const float* __restrict__ h1in = g_H1[(s & 1) ^ 1];
        for (int idx = tid; idx < 16 * 128; idx += 256) {
            int bb = idx >> 7, k = idx & 127;
            h0s[bb * 129 + k] = h0in[(b0 + bb) * 128 + k];
            h1s[bb * 129 + k] = h1in[(b0 + bb) * 128 + k];
        }
        for (int idx = tid; idx < 128 * 128; idx += 256) {
            int r = idx >> 7, k = idx & 127;
            int q = r >> 5, j = r & 31;
            Wsm[r * 129 + k] = Wih1[(q * 128 + j0 + j) * 128 + k];
        }
        __syncthreads();
        float acc[2][4] = {};
#pragma unroll 4
        for (int k = 0; k < 128; k++) {
            float w0 = Wsm[jj * 129 + k];
            float w1v = Wsm[(32 + jj) * 129 + k];
            float w2 = Wsm[(64 + jj) * 129 + k];
            float w3 = Wsm[(96 + jj) * 129 + k];
#pragma unroll
            for (int i = 0; i < 2; i++) {
                float h = h0s[(bg * 2 + i) * 129 + k];
                acc[i][0] += w0 * h;
                acc[i][1] += w1v * h;
                acc[i][2] += w2 * h;
                acc[i][3] += w3 * h;
            }
        }
        __syncthreads();
        for (int idx = tid; idx < 128 * 128; idx += 256) {
            int r = idx >> 7, k = idx & 127;
            int q = r >> 5, j = r & 31;
            Wsm[r * 129 + k] = Whh1[(q * 128 + j0 + j) * 128 + k];
        }
        __syncthreads();
#pragma unroll 4
        for (int k = 0; k < 128; k++) {
            float w0 = Wsm[jj * 129 + k];
            float w1v = Wsm[(32 + jj) * 129 + k];
            float w2 = Wsm[(64 + jj) * 129 + k];
            float w3 = Wsm[(96 + jj) * 129 + k];
#pragma unroll
            for (int i = 0; i < 2; i++) {
                float h = h1s[(bg * 2 + i) * 129 + k];
                acc[i][0] += w0 * h;
                acc[i][1] += w1v * h;
                acc[i][2] += w2 * h;
                acc[i][3] += w3 * h;
            }
        }
        const int j = j0 + jj;
#pragma unroll
        for (int i = 0; i < 2; i++) {
            int b = b0 + bg * 2 + i;
            float gi = acc[i][0] + g_b1l[j];
            float gf = acc[i][1] + g_b1l[128 + j];
            float gg = acc[i][2] + g_b1l[256 + j];
            float go = acc[i][3] + g_b1l[384 + j];
            float c = g_C1[b * 128 + j];
            c = sigm(gf) * c + sigm(gi) * tanhf(gg);
            float h = sigm(go) * tanhf(c);
            g_C1[b * 128 + j] = c;
            g_H1[s & 1][b * 128 + j] = h;
        }
    }
}

// ---------------- classifier ----------------
__global__ __launch_bounds__(256) void fc1_kernel(const float* __restrict__ bc1) {
    __shared__ float w[128 * 64];
    __shared__ float hsm[4 * 128];
    __shared__ float bsm[64];
    const int tid = threadIdx.x;
    const int b0 = blockIdx.x * 4;
    for (int idx = tid; idx < 8192; idx += 256) w[idx] = g_Wc1t[idx];
    if (tid < 64) bsm[tid] = bc1[tid];
    for (int idx = tid; idx < 512; idx += 256) hsm[idx] = g_H1[0][b0 * 128 + idx];
    __syncthreads();
    const int o = tid & 63, bb = tid >> 6;
    float s = bsm[o];
#pragma unroll 8
    for (int k = 0; k < 128; k++) s += hsm[bb * 128 + k] * w[k * 64 + o];
    g_hid[(b0 + bb) * 64 + o] = fmaxf(s, 0.0f);
}

__global__ __launch_bounds__(256) void fc2_kernel(const float* __restrict__ Wc2,
                                                  const float* __restrict__ bc2,
                                                  float* __restrict__ out) {
    __shared__ float w[11 * 64];
    __shared__ float bsm[11];
    __shared__ float hs[16 * 64];
    const int tid = threadIdx.x;
    const int b0 = blockIdx.x * 16;
    for (int idx = tid; idx < 704; idx += 256) w[idx] = Wc2[idx];
    if (tid < 11) bsm[tid] = bc2[tid];
    for (int idx = tid; idx < 1024; idx += 256) hs[idx] = g_hid[b0 * 64 + idx];
    __syncthreads();
    if (tid < 176) {
        int bb = tid / 11, c = tid - bb * 11;
        float s = bsm[c];
#pragma unroll 8
        for (int k = 0; k < 64; k++) s += hs[bb * 64 + k] * w[c * 64 + k];
        out[(b0 + bb) * 11 + c] = s;
    }
}

// ---------------- launch ----------------
extern "C" void kernel_launch(void* const* d_in, const int* in_sizes, int n_in,
                              void* d_out, int out_size) {
    const float* I    = (const float*)d_in[0];
    const float* Q    = (const float*)d_in[1];
    const float* E    = (const float*)d_in[2];
    const float* Wn1  = (const float*)d_in[3];
    const float* bn1  = (const float*)d_in[4];
    const float* Ws1  = (const float*)d_in[5];
    const float* bs1  = (const float*)d_in[6];
    const float* Wn2  = (const float*)d_in[7];
    const float* bn2  = (const float*)d_in[8];
    const float* Ws2  = (const float*)d_in[9];
    const float* bs2  = (const float*)d_in[10];
    const float* Wih0 = (const float*)d_in[11];
    const float* Whh0 = (const float*)d_in[12];
    const float* bih0 = (const float*)d_in[13];
    const float* bhh0 = (const float*)d_in[14];
    const float* Wih1 = (const float*)d_in[15];
    const float* Whh1 = (const float*)d_in[16];
    const float* bih1 = (const float*)d_in[17];
    const float* bhh1 = (const float*)d_in[18];
    const float* Wc1  = (const float*)d_in[19];
    const float* bc1  = (const float*)d_in[20];
    const float* Wc2  = (const float*)d_in[21];
    const float* bc2  = (const float*)d_in[22];
    float* out = (float*)d_out;

    const size_t gnn_smem  = GNN_SMEM_FLOATS * sizeof(float);   // 72704 B
    const size_t lstm_smem = LSTM_SMEM_FLOATS * sizeof(float);  // 82560 B
    cudaFuncSetAttribute(gnn_kernel, cudaFuncAttributeMaxDynamicSharedMemorySize, (int)gnn_smem);
    cudaFuncSetAttribute(lstm_step_kernel, cudaFuncAttributeMaxDynamicSharedMemorySize, (int)lstm_smem);

    prep_kernel<<<1, 256>>>(E, Wn1, bn1, Ws1, bs1, Wn2, bn2, Ws2, bs2,
                            Wih0, bih0, bhh0, bih1, bhh1, Wc1);
    zero_kernel<<<512, 256>>>();
    gnn_kernel<<<NBATCH * NP, 256, gnn_smem>>>(I, Q);
    xg0_kernel<<<dim3((NBATCH * NP) / 64, 8), 256>>>();
    for (int t = 0; t < 32; t++)
        lstm_step_kernel<<<384, 256, lstm_smem>>>(t, Whh0, Wih1, Whh1);
    fc1_kernel<<<NBATCH / 4, 256>>>(bc1);
    fc2_kernel<<<NBATCH / 16, 256>>>(Wc2, bc2, out);
    (void)in_sizes; (void)n_in; (void)out_size;
}

// round 6
// speedup vs baseline: 1.2166x; 1.2166x over previous
#include <cuda_runtime.h>
#include <math.h>

// ---------------- problem constants ----------------
#define NBATCH 1024
#define NP     31
#define RHD    128
#define NC     11

typedef unsigned long long ull;

// ---------------- f32x2 packed-FMA helpers ----------------
__device__ __forceinline__ ull pack2(float lo, float hi) {
    ull r; asm("mov.b64 %0, {%1,%2};" : "=l"(r) : "f"(lo), "f"(hi)); return r;
}
__device__ __forceinline__ void ffma2(ull& d, ull a, ull b) {
    asm("fma.rn.f32x2 %0, %1, %2, %0;" : "+l"(d) : "l"(a), "l"(b));
}
__device__ __forceinline__ float2 unpack2(ull v) {
    float2 r; asm("mov.b64 {%0,%1}, %2;" : "=f"(r.x), "=f"(r.y) : "l"(v)); return r;
}
__device__ __forceinline__ float sigm(float x) { return 1.0f / (1.0f + expf(-x)); }

// ---------------- device scratch ----------------
__device__ float g_awT[17 * 64];         // transposed banded adjacency * deg_inv: [k][i]
__device__ float g_b1[64];
__device__ float g_b2[64];
__device__ float g_w1[256];              // [Ws1t(2x64) ; Wn1t(2x64)]
__device__ float g_Ws2t[4096];           // [d][o]
__device__ float g_Wn2t[4096];
__device__ float g_b0c[512];
__device__ float g_b1l[512];
__device__ float g_Wih0t[64 * 512];      // [k][n]
__device__ float g_Wc1t[128 * 64];       // [k][o]
__device__ float g_feats[NBATCH * NP * 64];
__device__ float g_xg0[NBATCH * NP * 512];
__device__ float g_H0[2][NBATCH * RHD];
__device__ float g_C0[NBATCH * RHD];
__device__ float g_H1[2][NBATCH * RHD];
__device__ float g_C1[NBATCH * RHD];
__device__ float g_hid[NBATCH * 64];

// ---------------- prep ----------------
__global__ void prep_kernel(const float* __restrict__ E,
                            const float* __restrict__ Wn1, const float* __restrict__ bn1,
                            const float* __restrict__ Ws1, const float* __restrict__ bs1,
                            const float* __restrict__ Wn2, const float* __restrict__ bn2,
                            const float* __restrict__ Ws2, const float* __restrict__ bs2,
                            const float* __restrict__ Wih0,
                            const float* __restrict__ bih0, const float* __restrict__ bhh0,
                            const float* __restrict__ bih1, const float* __restrict__ bhh1,
                            const float* __restrict__ Wc1) {
    const int tid = threadIdx.x;
    if (tid < 64) {
        float row[17];
        float deg = 0.0f;
#pragma unroll
        for (int k = 0; k < 17; k++) {
            int j = tid - 8 + k;
            float a = 0.0f;
            if (j >= 0 && j < 64 && j != tid) a = 1.0f / (1.0f + expf(-E[tid * 64 + j]));
            row[k] = a;
            deg += a;
        }
        float inv = deg > 0.0f ? 1.0f / deg : 0.0f;
#pragma unroll
        for (int k = 0; k < 17; k++) g_awT[k * 64 + tid] = row[k] * inv;
        g_b1[tid] = bs1[tid] + bn1[tid];
        g_b2[tid] = bs2[tid] + bn2[tid];
        g_w1[tid]       = Ws1[tid * 2 + 0];
        g_w1[64 + tid]  = Ws1[tid * 2 + 1];
        g_w1[128 + tid] = Wn1[tid * 2 + 0];
        g_w1[192 + tid] = Wn1[tid * 2 + 1];
    }
    for (int idx = tid; idx < 4096; idx += 256) {
        int o = idx >> 6, d = idx & 63;
        g_Ws2t[d * 64 + o] = Ws2[idx];
        g_Wn2t[d * 64 + o] = Wn2[idx];
    }
    for (int idx = tid; idx < 512; idx += 256) {
        g_b0c[idx] = bih0[idx] + bhh0[idx];
        g_b1l[idx] = bih1[idx] + bhh1[idx];
    }
    for (int idx = tid; idx < 512 * 64; idx += 256) {
        int n = idx >> 6, k = idx & 63;
        g_Wih0t[k * 512 + n] = Wih0[idx];
    }
    for (int idx = tid; idx < 64 * 128; idx += 256) {
        int o = idx >> 7, k = idx & 127;
        g_Wc1t[k * 64 + o] = Wc1[idx];
    }
}

__global__ void zero_kernel() {
    int i = blockIdx.x * blockDim.x + threadIdx.x;
    if (i < NBATCH * RHD) {
        g_H0[1][i] = 0.0f;
        g_C0[i]    = 0.0f;
        g_H1[1][i] = 0.0f;
        g_C1[i]    = 0.0f;
    }
}

// ---------------- fused GNN ----------------
// smem floats: x1[4096] n1[4096] Ws[4096] Wn[4096] awT[1088] x0[128] n0[128] w1[256] b1s[64] b2s[64]
#define GNN_SMEM_FLOATS 18112
__global__ __launch_bounds__(256) void gnn_kernel(const float* __restrict__ I,
                                                  const float* __restrict__ Q) {
    extern __shared__ float sm[];
    float* x1  = sm;
    float* n1  = sm + 4096;
    float* Ws  = sm + 8192;
    float* Wn  = sm + 12288;
    float* awT = sm + 16384;
    float* x0  = sm + 17472;
    float* n0  = sm + 17600;
    float* w1  = sm + 17728;
    float* b1s = sm + 17984;
    float* b2s = sm + 18048;

    const int tid = threadIdx.x;
    const int bp  = blockIdx.x;
    const int b   = bp / NP;
    const int p   = bp - b * NP;

    for (int idx = tid; idx < 1024; idx += 256) {
        ((float4*)Ws)[idx] = ((const float4*)g_Ws2t)[idx];
        ((float4*)Wn)[idx] = ((const float4*)g_Wn2t)[idx];
    }
    for (int idx = tid; idx < 1088; idx += 256) awT[idx] = g_awT[idx];
    w1[tid] = g_w1[tid];
    if (tid < 64) {
        b1s[tid] = g_b1[tid];
        b2s[tid] = g_b2[tid];
        int pos = b * 1024 + p * 32 + tid;
        x0[tid * 2 + 0] = I[pos];
        x0[tid * 2 + 1] = Q[pos];
    }
    __syncthreads();

    // neigh0[i][dd] (dd=2)
    if (tid < 128) {
        int i = tid >> 1, dd = tid & 1;
        float s = 0.0f;
#pragma unroll
        for (int k = 0; k < 17; k++) {
            int j = i - 8 + k;
            j = max(0, min(63, j));
            s += awT[k * 64 + i] * x0[j * 2 + dd];
        }
        n0[tid] = s;
    }
    __syncthreads();

    // SAGE layer 1
    {
        const int o = tid & 63, ig = tid >> 6;
        const float ws0 = w1[o], ws1 = w1[64 + o], wn0 = w1[128 + o], wn1 = w1[192 + o];
        const float bb = b1s[o];
#pragma unroll
        for (int ii = 0; ii < 16; ii++) {
            int i = ig * 16 + ii;
            float v = bb + x0[i * 2] * ws0 + x0[i * 2 + 1] * ws1
                         + n0[i * 2] * wn0 + n0[i * 2 + 1] * wn1;
            x1[i * 64 + o] = fmaxf(v, 0.0f);
        }
    }
    __syncthreads();

    // banded conv -> n1, sliding-window registers (16 i per thread)
    {
        const int d  = tid & 63;
        const int ig = tid >> 6;      // 0..3
        const int i0c = ig * 16;
        float xwin[16];
#pragma unroll
        for (int w = 0; w < 16; w++) {
            int j = i0c - 8 + w;
            j = max(0, min(63, j));
            xwin[w] = x1[j * 64 + d];
        }
        float accv[16];
#pragma unroll
        for (int w = 0; w < 16; w++) accv[w] = 0.0f;
#pragma unroll
        for (int k = 0; k < 17; k++) {
#pragma unroll
            for (int ii = 0; ii < 16; ii++)
                accv[ii] += awT[k * 64 + i0c + ii] * xwin[ii];
            if (k < 16) {
#pragma unroll
                for (int w = 0; w < 15; w++) xwin[w] = xwin[w + 1];
                int j = min(63, i0c + 8 + k);
                xwin[15] = x1[j * 64 + d];
            }
        }
#pragma unroll
        for (int ii = 0; ii < 16; ii++) n1[(i0c + ii) * 64 + d] = accv[ii];
    }
    __syncthreads();

    // SAGE layer 2 GEMM with f32x2 (acc packed along o), then node-sum
    {
        const int i0 = (tid >> 4) * 4;
        const int o0 = (tid & 15) * 4;
        ull acc2[4][2];
#pragma unroll
        for (int ii = 0; ii < 4; ii++) { acc2[ii][0] = 0ull; acc2[ii][1] = 0ull; }
#pragma unroll 2
        for (int d = 0; d < 64; d += 4) {
            ulonglong2 wsv[4], wnv[4];
#pragma unroll
            for (int dd = 0; dd < 4; dd++) {
                wsv[dd] = *(const ulonglong2*)(Ws + (d + dd) * 64 + o0);
                wnv[dd] = *(const ulonglong2*)(Wn + (d + dd) * 64 + o0);
            }
#pragma unroll
            for (int ii = 0; ii < 4; ii++) {
                const float4 a = *(const float4*)(x1 + (i0 + ii) * 64 + d);
                const float4 e = *(const float4*)(n1 + (i0 + ii) * 64 + d);
                ull p;
                p = pack2(a.x, a.x); ffma2(acc2[ii][0], p, wsv[0].x); ffma2(acc2[ii][1], p, wsv[0].y);
                p = pack2(e.x, e.x); ffma2(acc2[ii][0], p, wnv[0].x); ffma2(acc2[ii][1], p, wnv[0].y);
                p = pack2(a.y, a.y); ffma2(acc2[ii][0], p, wsv[1].x); ffma2(acc2[ii][1], p, wsv[1].y);
                p = pack2(e.y, e.y); ffma2(acc2[ii][0], p, wnv[1].x); ffma2(acc2[ii][1], p, wnv[1].y);
                p = pack2(a.z, a.z); ffma2(acc2[ii][0], p, wsv[2].x); ffma2(acc2[ii][1], p, wsv[2].y);
                p = pack2(e.z, e.z); ffma2(acc2[ii][0], p, wnv[2].x); ffma2(acc2[ii][1], p, wnv[2].y);
                p = pack2(a.w, a.w); ffma2(acc2[ii][0], p, wsv[3].x); ffma2(acc2[ii][1], p, wsv[3].y);
                p = pack2(e.w, e.w); ffma2(acc2[ii][0], p, wnv[3].x); ffma2(acc2[ii][1], p, wnv[3].y);
            }
        }
        float fs[4] = {0.f, 0.f, 0.f, 0.f};
        const float bb0 = b2s[o0], bb1 = b2s[o0 + 1], bb2 = b2s[o0 + 2], bb3 = b2s[o0 + 3];
#pragma unroll
        for (int ii = 0; ii < 4; ii++) {
            float2 v01 = unpack2(acc2[ii][0]);
            float2 v23 = unpack2(acc2[ii][1]);
            fs[0] += fmaxf(v01.x + bb0, 0.0f);
            fs[1] += fmaxf(v01.y + bb1, 0.0f);
            fs[2] += fmaxf(v23.x + bb2, 0.0f);
            fs[3] += fmaxf(v23.y + bb3, 0.0f);
        }
        __syncthreads();   // done reading x1 — reuse as reduction buffer
        const int ig = tid >> 4;
#pragma unroll
        for (int oo = 0; oo < 4; oo++) x1[ig * 64 + o0 + oo] = fs[oo];
    }
    __syncthreads();
    if (tid < 64) {
        float s = 0.0f;
#pragma unroll
        for (int g = 0; g < 16; g++) s += x1[g * 64 + tid];
        g_feats[bp * 64 + tid] = s;
    }
}

// ---------------- xg0 = feats @ Wih0^T + bias : [31744 x 512], K=64 ----------------
__global__ __launch_bounds__(256) void xg0_kernel() {
    __shared__ float As[64 * 64];
    __shared__ float Bs[64 * 64];
    __shared__ float bsm[64];
    const int m0 = blockIdx.x * 64;
    const int n0 = blockIdx.y * 64;
    const int tid = threadIdx.x;
    for (int idx = tid; idx < 1024; idx += 256)
        ((float4*)As)[idx] = *(const float4*)(g_feats + (m0 + (idx >> 4)) * 64 + (idx & 15) * 4);
    for (int idx = tid; idx < 1024; idx += 256)
        ((float4*)Bs)[idx] = *(const float4*)(g_Wih0t + (idx >> 4) * 512 + n0 + (idx & 15) * 4);
    if (tid < 64) bsm[tid] = g_b0c[n0 + tid];
    __syncthreads();
    const int mi0 = (tid >> 4) * 4;
    const int ni0 = (tid & 15) * 4;
    ull acc[4][2];
#pragma unroll
    for (int ii = 0; ii < 4; ii++) { acc[ii][0] = 0ull; acc[ii][1] = 0ull; }
#pragma unroll 2
    for (int k = 0; k < 64; k += 4) {
        ulonglong2 bv[4];
#pragma unroll
        for (int kk = 0; kk < 4; kk++) bv[kk] = *(const ulonglong2*)(Bs + (k + kk) * 64 + ni0);
#pragma unroll
        for (int ii = 0; ii < 4; ii++) {
            const float4 a = *(const float4*)(As + (mi0 + ii) * 64 + k);
            ull p;
            p = pack2(a.x, a.x); ffma2(acc[ii][0], p, bv[0].x); ffma2(acc[ii][1], p, bv[0].y);
            p = pack2(a.y, a.y); ffma2(acc[ii][0], p, bv[1].x); ffma2(acc[ii][1], p, bv[1].y);
            p = pack2(a.z, a.z); ffma2(acc[ii][0], p, bv[2].x); ffma2(acc[ii][1], p, bv[2].y);
            p = pack2(a.w, a.w); ffma2(acc[ii][0], p, bv[3].x); ffma2(acc[ii][1], p, bv[3].y);
        }
    }
#pragma unroll
    for (int ii = 0; ii < 4; ii++) {
        float2 v01 = unpack2(acc[ii][0]);
        float2 v23 = unpack2(acc[ii][1]);
        float* dst = g_xg0 + (m0 + mi0 + ii) * 512 + n0 + ni0;
        dst[0] = v01.x + bsm[ni0 + 0];
        dst[1] = v01.y + bsm[ni0 + 1];
        dst[2] = v23.x + bsm[ni0 + 2];
        dst[3] = v23.y + bsm[ni0 + 3];
    }
}

// ---------------- pipelined LSTM step ----------------
// Wp layout: [kp 0..63][pitch 258 floats] holding interleaved (k even, k odd) pairs:
//   Wp[kp*258 + r*2 + par] = W[row r][k = 2*kp+par],  r = q*32 + j  (q=gate, j=local col)
// smem floats: Wp 16512 + h-buffers 4096 = 20608
#define LSTM_SMEM_FLOATS 20608
__global__ __launch_bounds__(256) void lstm_step_kernel(int t,
                                                        const float* __restrict__ Whh0,
                                                        const float* __restrict__ Wih1,
                                                        const float* __restrict__ Whh1) {
    extern __shared__ float sm[];
    const int tid = threadIdx.x;
    const int jj = tid & 31;
    const int bg = tid >> 5;  // warp id 0..7

    if (blockIdx.x < 128) {
        // ---- layer0, step t ----
        if (t > 30) return;
        const int b0 = (blockIdx.x >> 2) * 32;
        const int j0 = (blockIdx.x & 3) * 32;
        float* Wp = sm;                 // 64*258
        float* hs = sm + 16512;         // [32][128]
        const float* __restrict__ hprev = g_H0[(t + 1) & 1];
        for (int idx = tid; idx < 32 * 128; idx += 256) {
            int bb = idx >> 7, k = idx & 127;
            hs[bb * 128 + k] = hprev[(b0 + bb) * 128 + k];
        }
        for (int idx = tid; idx < 128 * 128; idx += 256) {
            int k = idx & 127, r = idx >> 7;
            int q = r >> 5, j = r & 31;
            Wp[(k >> 1) * 258 + r * 2 + (k & 1)] = Whh0[(q * 128 + j0 + j) * 128 + k];
        }
        __syncthreads();
        ull acc[4][4];
#pragma unroll
        for (int i = 0; i < 4; i++)
#pragma unroll
            for (int q = 0; q < 4; q++) acc[i][q] = 0ull;
#pragma unroll 4
        for (int kp = 0; kp < 64; kp++) {
            const float* wrow = Wp + kp * 258 + jj * 2;
            const ull w0 = *(const ull*)(wrow);
            const ull w1v = *(const ull*)(wrow + 64);
            const ull w2 = *(const ull*)(wrow + 128);
            const ull w3 = *(const ull*)(wrow + 192);
#pragma unroll
            for (int i = 0; i < 4; i++) {
                const ull h = *(const ull*)(hs + (bg * 4 + i) * 128 + kp * 2);
                ffma2(acc[i][0], h, w0);
                ffma2(acc[i][1], h, w1v);
                ffma2(acc[i][2], h, w2);
                ffma2(acc[i][3], h, w3);
            }
        }
        const int j = j0 + jj;
#pragma unroll
        for (int i = 0; i < 4; i++) {
            int b = b0 + bg * 4 + i;
            const float* xg = g_xg0 + (b * NP + t) * 512;
            float2 s0 = unpack2(acc[i][0]);
            float2 s1 = unpack2(acc[i][1]);
            float2 s2 = unpack2(acc[i][2]);
            float2 s3 = unpack2(acc[i][3]);
            float gi = s0.x + s0.y + xg[j];
            float gf = s1.x + s1.y + xg[128 + j];
            float gg = s2.x + s2.y + xg[256 + j];
            float go = s3.x + s3.y + xg[384 + j];
            float c = g_C0[b * 128 + j];
            c = sigm(gf) * c + sigm(gi) * tanhf(gg);
            float h = sigm(go) * tanhf(c);
            g_C0[b * 128 + j] = c;
            g_H0[t & 1][b * 128 + j] = h;
        }
    } else {
        // ---- layer1, step s = t-1 ----
        const int s = t - 1;
        if (s < 0) return;
        const int blk = blockIdx.x - 128;   // 0..255
        const int b0 = (blk >> 2) * 16;
        const int j0 = (blk & 3) * 32;
        float* Wp  = sm;
        float* h0s = sm + 16512;            // [16][128]
        float* h1s = h0s + 2048;            // [16][128]
        const float* __restrict__ h0in = g_H0[s & 1];
        const float* __restrict__ h1in = g_H1[(s & 1) ^ 1];
        for (int idx = tid; idx < 16 * 128; idx += 256) {
            int bb = idx >> 7, k = idx & 127;
            h0s[bb * 128 + k] = h0in[(b0 + bb) * 128 + k];
            h1s[bb * 128 + k] = h1in[(b0 + bb) * 128 + k];
        }
        for (int idx = tid; idx < 128 * 128; idx += 256) {
            int k = idx & 127, r = idx >> 7;
            int q = r >> 5, j = r & 31;
            Wp[(k >> 1) * 258 + r * 2 + (k & 1)] = Wih1[(q * 128 + j0 + j) * 128 + k];
        }
        __syncthreads();
        ull acc[2][4];
#pragma unroll
        for (int i = 0; i < 2; i++)
#pragma unroll
            for (int q = 0; q < 4; q++) acc[i][q] = 0ull;
#pragma unroll 4
        for (int kp = 0; kp < 64; kp++) {
            const float* wrow = Wp + kp * 258 + jj * 2;
            const ull w0 = *(const ull*)(wrow);
            const ull w1v = *(const ull*)(wrow + 64);
            const ull w2 = *(const ull*)(wrow + 128);
            const ull w3 = *(const ull*)(wrow + 192);
#pragma unroll
            for (int i = 0; i < 2; i++) {
                const ull h = *(const ull*)(h0s + (bg * 2 + i) * 128 + kp * 2);
                ffma2(acc[i][0], h, w0);
                ffma2(acc[i][1], h, w1v);
                ffma2(acc[i][2], h, w2);
                ffma2(acc[i][3], h, w3);
            }
        }
        __syncthreads();
        for (int idx = tid; idx < 128 * 128; idx += 256) {
            int k = idx & 127, r = idx >> 7;
            int q = r >> 5, j = r & 31;
            Wp[(k >> 1) * 258 + r * 2 + (k & 1)] = Whh1[(q * 128 + j0 + j) * 128 + k];
        }
        __syncthreads();
#pragma unroll 4
        for (int kp = 0; kp < 64; kp++) {
            const float* wrow = Wp + kp * 258 + jj * 2;
            const ull w0 = *(const ull*)(wrow);
            const ull w1v = *(const ull*)(wrow + 64);
            const ull w2 = *(const ull*)(wrow + 128);
            const ull w3 = *(const ull*)(wrow + 192);
#pragma unroll
            for (int i = 0; i < 2; i++) {
                const ull h = *(const ull*)(h1s + (bg * 2 + i) * 128 + kp * 2);
                ffma2(acc[i][0], h, w0);
                ffma2(acc[i][1], h, w1v);
                ffma2(acc[i][2], h, w2);
                ffma2(acc[i][3], h, w3);
            }
        }
        const int j = j0 + jj;
#pragma unroll
        for (int i = 0; i < 2; i++) {
            int b = b0 + bg * 2 + i;
            float2 s0 = unpack2(acc[i][0]);
            float2 s1 = unpack2(acc[i][1]);
            float2 s2 = unpack2(acc[i][2]);
            float2 s3 = unpack2(acc[i][3]);
            float gi = s0.x + s0.y + g_b1l[j];
            float gf = s1.x + s1.y + g_b1l[128 + j];
            float gg = s2.x + s2.y + g_b1l[256 + j];
            float go = s3.x + s3.y + g_b1l[384 + j];
            float c = g_C1[b * 128 + j];
            c = sigm(gf) * c + sigm(gi) * tanhf(gg);
            float h = sigm(go) * tanhf(c);
            g_C1[b * 128 + j] = c;
            g_H1[s & 1][b * 128 + j] = h;
        }
    }
}

// ---------------- classifier ----------------
__global__ __launch_bounds__(256) void fc1_kernel(const float* __restrict__ bc1) {
    __shared__ float w[128 * 64];
    __shared__ float hsm[4 * 128];
    __shared__ float bsm[64];
    const int tid = threadIdx.x;
    const int b0 = blockIdx.x * 4;
    for (int idx = tid; idx < 8192; idx += 256) w[idx] = g_Wc1t[idx];
    if (tid < 64) bsm[tid] = bc1[tid];
    for (int idx = tid; idx < 512; idx += 256) hsm[idx] = g_H1[0][b0 * 128 + idx];
    __syncthreads();
    const int o = tid & 63, bb = tid >> 6;
    float s = bsm[o];
#pragma unroll 8
    for (int k = 0; k < 128; k++) s += hsm[bb * 128 + k] * w[k * 64 + o];
    g_hid[(b0 + bb) * 64 + o] = fmaxf(s, 0.0f);
}

__global__ __launch_bounds__(256) void fc2_kernel(const float* __restrict__ Wc2,
                                                  const float* __restrict__ bc2,
                                                  float* __restrict__ out) {
    __shared__ float w[11 * 64];
    __shared__ float bsm[11];
    __shared__ float hs[16 * 64];
    const int tid = threadIdx.x;
    const int b0 = blockIdx.x * 16;
    for (int idx = tid; idx < 704; idx += 256) w[idx] = Wc2[idx];
    if (tid < 11) bsm[tid] = bc2[tid];
    for (int idx = tid; idx < 1024; idx += 256) hs[idx] = g_hid[b0 * 64 + idx];
    __syncthreads();
    if (tid < 176) {
        int bb = tid / 11, c = tid - bb * 11;
        float s = bsm[c];
#pragma unroll 8
        for (int k = 0; k < 64; k++) s += hs[bb * 64 + k] * w[c * 64 + k];
        out[(b0 + bb) * 11 + c] = s;
    }
}

// ---------------- launch ----------------
extern "C" void kernel_launch(void* const* d_in, const int* in_sizes, int n_in,
                              void* d_out, int out_size) {
    const float* I    = (const float*)d_in[0];
    const float* Q    = (const float*)d_in[1];
    const float* E    = (const float*)d_in[2];
    const float* Wn1  = (const float*)d_in[3];
    const float* bn1  = (const float*)d_in[4];
    const float* Ws1  = (const float*)d_in[5];
    const float* bs1  = (const float*)d_in[6];
    const float* Wn2  = (const float*)d_in[7];
    const float* bn2  = (const float*)d_in[8];
    const float* Ws2  = (const float*)d_in[9];
    const float* bs2  = (const float*)d_in[10];
    const float* Wih0 = (const float*)d_in[11];
    const float* Whh0 = (const float*)d_in[12];
    const float* bih0 = (const float*)d_in[13];
    const float* bhh0 = (const float*)d_in[14];
    const float* Wih1 = (const float*)d_in[15];
    const float* Whh1 = (const float*)d_in[16];
    const float* bih1 = (const float*)d_in[17];
    const float* bhh1 = (const float*)d_in[18];
    const float* Wc1  = (const float*)d_in[19];
    const float* bc1  = (const float*)d_in[20];
    const float* Wc2  = (const float*)d_in[21];
    const float* bc2  = (const float*)d_in[22];
    float* out = (float*)d_out;

    const size_t gnn_smem  = GNN_SMEM_FLOATS * sizeof(float);   // 72448 B
    const size_t lstm_smem = LSTM_SMEM_FLOATS * sizeof(float);  // 82432 B
    cudaFuncSetAttribute(gnn_kernel, cudaFuncAttributeMaxDynamicSharedMemorySize, (int)gnn_smem);
    cudaFuncSetAttribute(lstm_step_kernel, cudaFuncAttributeMaxDynamicSharedMemorySize, (int)lstm_smem);

    prep_kernel<<<1, 256>>>(E, Wn1, bn1, Ws1, bs1, Wn2, bn2, Ws2, bs2,
                            Wih0, bih0, bhh0, bih1, bhh1, Wc1);
    zero_kernel<<<512, 256>>>();
    gnn_kernel<<<NBATCH * NP, 256, gnn_smem>>>(I, Q);
    xg0_kernel<<<dim3((NBATCH * NP) / 64, 8), 256>>>();
    for (int t = 0; t < 32; t++)
        lstm_step_kernel<<<384, 256, lstm_smem>>>(t, Whh0, Wih1, Whh1);
    fc1_kernel<<<NBATCH / 4, 256>>>(bc1);
    fc2_kernel<<<NBATCH / 16, 256>>>(Wc2, bc2, out);
    (void)in_sizes; (void)n_in; (void)out_size;
}

// round 7
// speedup vs baseline: 1.2863x; 1.0573x over previous
#include <cuda_runtime.h>
#include <math.h>

// ---------------- problem constants ----------------
#define NBATCH 1024
#define NP     31
#define RHD    128
#define NC     11

typedef unsigned long long ull;

// ---------------- f32x2 packed-FMA helpers ----------------
__device__ __forceinline__ void ffma2(ull& d, ull a, ull b) {
    asm("fma.rn.f32x2 %0, %1, %2, %0;" : "+l"(d) : "l"(a), "l"(b));
}
__device__ __forceinline__ float2 unpack2(ull v) {
    float2 r; asm("mov.b64 {%0,%1}, %2;" : "=f"(r.x), "=f"(r.y) : "l"(v)); return r;
}
__device__ __forceinline__ float sigm(float x) { return 1.0f / (1.0f + expf(-x)); }

// ---------------- device scratch ----------------
__device__ float g_awT[17 * 64];          // [k][i] banded adj * deg_inv (scalar)
__device__ float g_awT2[17 * 64 * 2];     // [k][i] duplicated pairs (ull view)
__device__ float g_b1[64];
__device__ float g_b2[64];
__device__ float g_w1[256];               // [Ws1t(2x64) ; Wn1t(2x64)]
__device__ float g_Ws2p[4096];            // packed: [dp][o*2+par], par = d&1
__device__ float g_Wn2p[4096];
__device__ float g_b0c[512];
__device__ float g_b1l[512];
__device__ float g_Wih0t[64 * 512];       // [k][n]
__device__ float g_Wc1t[128 * 64];        // [k][o]
__device__ float g_feats[NBATCH * NP * 64];
__device__ float g_xg0[NBATCH * NP * 512];
__device__ float g_H0[2][NBATCH * RHD];
__device__ float g_C0[NBATCH * RHD];
__device__ float g_H1[2][NBATCH * RHD];
__device__ float g_C1[NBATCH * RHD];
__device__ float g_hid[NBATCH * 64];

// ---------------- prep ----------------
__global__ void prep_kernel(const float* __restrict__ E,
                            const float* __restrict__ Wn1, const float* __restrict__ bn1,
                            const float* __restrict__ Ws1, const float* __restrict__ bs1,
                            const float* __restrict__ Wn2, const float* __restrict__ bn2,
                            const float* __restrict__ Ws2, const float* __restrict__ bs2,
                            const float* __restrict__ Wih0,
                            const float* __restrict__ bih0, const float* __restrict__ bhh0,
                            const float* __restrict__ bih1, const float* __restrict__ bhh1,
                            const float* __restrict__ Wc1) {
    const int tid = threadIdx.x;
    if (tid < 64) {
        float row[17];
        float deg = 0.0f;
#pragma unroll
        for (int k = 0; k < 17; k++) {
            int j = tid - 8 + k;
            float a = 0.0f;
            if (j >= 0 && j < 64 && j != tid) a = 1.0f / (1.0f + expf(-E[tid * 64 + j]));
            row[k] = a;
            deg += a;
        }
        float inv = deg > 0.0f ? 1.0f / deg : 0.0f;
#pragma unroll
        for (int k = 0; k < 17; k++) g_awT[k * 64 + tid] = row[k] * inv;
        g_b1[tid] = bs1[tid] + bn1[tid];
        g_b2[tid] = bs2[tid] + bn2[tid];
        g_w1[tid]       = Ws1[tid * 2 + 0];
        g_w1[64 + tid]  = Ws1[tid * 2 + 1];
        g_w1[128 + tid] = Wn1[tid * 2 + 0];
        g_w1[192 + tid] = Wn1[tid * 2 + 1];
    }
    __syncthreads();
    for (int idx = tid; idx < 17 * 64; idx += 256) {
        float v = g_awT[idx];
        g_awT2[idx * 2 + 0] = v;
        g_awT2[idx * 2 + 1] = v;
    }
    // packed SAGE2 weights: g_*p[dp*128 + o*2 + par] = W[o][2dp+par]
    for (int idx = tid; idx < 4096; idx += 256) {
        int dp = idx >> 7, rem = idx & 127;
        int o = rem >> 1, par = rem & 1;
        g_Ws2p[idx] = Ws2[o * 64 + 2 * dp + par];
        g_Wn2p[idx] = Wn2[o * 64 + 2 * dp + par];
    }
    for (int idx = tid; idx < 512; idx += 256) {
        g_b0c[idx] = bih0[idx] + bhh0[idx];
        g_b1l[idx] = bih1[idx] + bhh1[idx];
    }
    for (int idx = tid; idx < 512 * 64; idx += 256) {
        int n = idx >> 6, k = idx & 63;
        g_Wih0t[k * 512 + n] = Wih0[idx];
    }
    for (int idx = tid; idx < 64 * 128; idx += 256) {
        int o = idx >> 7, k = idx & 127;
        g_Wc1t[k * 64 + o] = Wc1[idx];
    }
}

__global__ void zero_kernel() {
    int i = blockIdx.x * blockDim.x + threadIdx.x;
    if (i < NBATCH * RHD) {
        g_H0[1][i] = 0.0f;
        g_C0[i]    = 0.0f;
        g_H1[1][i] = 0.0f;
        g_C1[i]    = 0.0f;
    }
}

// ---------------- fused GNN: 2 patches per CTA ----------------
// smem floats: x1[4096] n1[4096] Wsp[4096] Wnp[4096] awT2[2176] x0[128] n0[128]
//              w1[256] b1s[64] b2s[64]  = 19200 floats (76.8 KB)
#define GNN_SMEM_FLOATS 19200
__global__ __launch_bounds__(256) void gnn_kernel(const float* __restrict__ I,
                                                  const float* __restrict__ Q) {
    extern __shared__ float sm[];
    float* x1   = sm;
    float* n1   = sm + 4096;
    float* Wsp  = sm + 8192;
    float* Wnp  = sm + 12288;
    float* awT2 = sm + 16384;
    float* x0   = sm + 18560;
    float* n0   = sm + 18688;
    float* w1   = sm + 18816;
    float* b1s  = sm + 19072;
    float* b2s  = sm + 19136;

    const int tid = threadIdx.x;

    for (int idx = tid; idx < 1024; idx += 256) {
        ((float4*)Wsp)[idx] = ((const float4*)g_Ws2p)[idx];
        ((float4*)Wnp)[idx] = ((const float4*)g_Wn2p)[idx];
    }
    for (int idx = tid; idx < 2176; idx += 256) awT2[idx] = g_awT2[idx];
    w1[tid] = g_w1[tid];
    if (tid < 64) {
        b1s[tid] = g_b1[tid];
        b2s[tid] = g_b2[tid];
    }

#pragma unroll 1
    for (int pp = 0; pp < 2; pp++) {
        const int gp = blockIdx.x * 2 + pp;   // global patch index = b*31 + p
        const int b  = gp / NP;
        const int p  = gp - b * NP;
        __syncthreads();
        if (tid < 64) {
            int pos = b * 1024 + p * 32 + tid;
            x0[tid * 2 + 0] = I[pos];
            x0[tid * 2 + 1] = Q[pos];
        }
        __syncthreads();

        // neigh0[i][dd] (dd=2)
        if (tid < 128) {
            int i = tid >> 1, dd = tid & 1;
            float s = 0.0f;
#pragma unroll
            for (int k = 0; k < 17; k++) {
                int j = i - 8 + k;
                j = max(0, min(63, j));
                s += awT2[(k * 64 + i) * 2] * x0[j * 2 + dd];
            }
            n0[tid] = s;
        }
        __syncthreads();

        // SAGE layer 1
        {
            const int o = tid & 63, ig = tid >> 6;
            const float ws0 = w1[o], ws1 = w1[64 + o], wn0 = w1[128 + o], wn1 = w1[192 + o];
            const float bb = b1s[o];
#pragma unroll
            for (int ii = 0; ii < 16; ii++) {
                int i = ig * 16 + ii;
                float v = bb + x0[i * 2] * ws0 + x0[i * 2 + 1] * ws1
                             + n0[i * 2] * wn0 + n0[i * 2 + 1] * wn1;
                x1[i * 64 + o] = fmaxf(v, 0.0f);
            }
        }
        __syncthreads();

        // banded conv -> n1, f32x2 over d-pairs (thread: dp = lane 0..31, 8 i's)
        {
            const int dp = tid & 31;
            const int ig = tid >> 5;     // 0..7
#pragma unroll
            for (int ii = 0; ii < 8; ii++) {
                const int i = ig * 8 + ii;
                ull acc = 0ull;
#pragma unroll
                for (int k = 0; k < 17; k++) {
                    int j = i - 8 + k;
                    j = max(0, min(63, j));
                    const ull aw = *(const ull*)(awT2 + (k * 64 + i) * 2);  // broadcast
                    const ull xp = *(const ull*)(x1 + j * 64 + 2 * dp);
                    ffma2(acc, aw, xp);
                }
                *(ull*)(n1 + i * 64 + 2 * dp) = acc;
            }
        }
        __syncthreads();

        // SAGE layer 2 GEMM: K-packed f32x2 (pair lanes = d even/odd), o strided by 16
        {
            const int ol = tid & 15;
            const int i0 = (tid >> 4) * 4;
            ull acc[4][4];
#pragma unroll
            for (int ii = 0; ii < 4; ii++)
#pragma unroll
                for (int c = 0; c < 4; c++) acc[ii][c] = 0ull;
#pragma unroll 2
            for (int dp = 0; dp < 32; dp++) {
                ull ws[4], wn[4];
#pragma unroll
                for (int c = 0; c < 4; c++) {
                    ws[c] = *(const ull*)(Wsp + dp * 128 + (ol + 16 * c) * 2);
                    wn[c] = *(const ull*)(Wnp + dp * 128 + (ol + 16 * c) * 2);
                }
#pragma unroll
                for (int ii = 0; ii < 4; ii++) {
                    const ull a = *(const ull*)(x1 + (i0 + ii) * 64 + 2 * dp);
                    const ull e = *(const ull*)(n1 + (i0 + ii) * 64 + 2 * dp);
#pragma unroll
                    for (int c = 0; c < 4; c++) {
                        ffma2(acc[ii][c], a, ws[c]);
                        ffma2(acc[ii][c], e, wn[c]);
                    }
                }
            }
            float fs[4] = {0.f, 0.f, 0.f, 0.f};
#pragma unroll
            for (int c = 0; c < 4; c++) {
                const float bb = b2s[ol + 16 * c];
#pragma unroll
                for (int ii = 0; ii < 4; ii++) {
                    float2 v = unpack2(acc[ii][c]);
                    fs[c] += fmaxf(v.x + v.y + bb, 0.0f);
                }
            }
            __syncthreads();   // done reading x1 — reuse as reduction buffer
            const int ig = tid >> 4;
#pragma unroll
            for (int c = 0; c < 4; c++) x1[ig * 64 + ol + 16 * c] = fs[c];
        }
        __syncthreads();
        if (tid < 64) {
            float s = 0.0f;
#pragma unroll
            for (int g = 0; g < 16; g++) s += x1[g * 64 + tid];
            g_feats[gp * 64 + tid] = s;
        }
    }
}

// ---------------- xg0 = feats @ Wih0^T + bias : [31744 x 512], K=64 ----------------
__global__ __launch_bounds__(256) void xg0_kernel() {
    __shared__ float As[64 * 64];
    __shared__ float Bs[64 * 64];
    __shared__ float bsm[64];
    const int m0 = blockIdx.x * 64;
    const int n0 = blockIdx.y * 64;
    const int tid = threadIdx.x;
    for (int idx = tid; idx < 1024; idx += 256)
        ((float4*)As)[idx] = *(const float4*)(g_feats + (m0 + (idx >> 4)) * 64 + (idx & 15) * 4);
    for (int idx = tid; idx < 1024; idx += 256)
        ((float4*)Bs)[idx] = *(const float4*)(g_Wih0t + (idx >> 4) * 512 + n0 + (idx & 15) * 4);
    if (tid < 64) bsm[tid] = g_b0c[n0 + tid];
    __syncthreads();
    const int mi0 = (tid >> 4) * 4;
    const int ni0 = (tid & 15) * 4;
    ull acc[4][2];
#pragma unroll
    for (int ii = 0; ii < 4; ii++) { acc[ii][0] = 0ull; acc[ii][1] = 0ull; }
#pragma unroll 2
    for (int k = 0; k < 64; k += 4) {
        ulonglong2 bv[4];
#pragma unroll
        for (int kk = 0; kk < 4; kk++) bv[kk] = *(const ulonglong2*)(Bs + (k + kk) * 64 + ni0);
#pragma unroll
        for (int ii = 0; ii < 4; ii++) {
            const float4 a = *(const float4*)(As + (mi0 + ii) * 64 + k);
            ull p;
            asm("mov.b64 %0, {%1,%1};" : "=l"(p) : "f"(a.x));
            ffma2(acc[ii][0], p, bv[0].x); ffma2(acc[ii][1], p, bv[0].y);
            asm("mov.b64 %0, {%1,%1};" : "=l"(p) : "f"(a.y));
            ffma2(acc[ii][0], p, bv[1].x); ffma2(acc[ii][1], p, bv[1].y);
            asm("mov.b64 %0, {%1,%1};" : "=l"(p) : "f"(a.z));
            ffma2(acc[ii][0], p, bv[2].x); ffma2(acc[ii][1], p, bv[2].y);
            asm("mov.b64 %0, {%1,%1};" : "=l"(p) : "f"(a.w));
            ffma2(acc[ii][0], p, bv[3].x); ffma2(acc[ii][1], p, bv[3].y);
        }
    }
#pragma unroll
    for (int ii = 0; ii < 4; ii++) {
        float2 v01 = unpack2(acc[ii][0]);
        float2 v23 = unpack2(acc[ii][1]);
        float* dst = g_xg0 + (m0 + mi0 + ii) * 512 + n0 + ni0;
        dst[0] = v01.x + bsm[ni0 + 0];
        dst[1] = v01.y + bsm[ni0 + 1];
        dst[2] = v23.x + bsm[ni0 + 2];
        dst[3] = v23.y + bsm[ni0 + 3];
    }
}

// ---------------- pipelined LSTM step ----------------
// layer0: blocks [0,64)   — b-tile 64, j-tile 32, 8 batches/thread
// layer1: blocks [64,192) — b-tile 32, j-tile 32, 4 batches/thread
// smem: Wp 64*258 = 16512 + h buffers 8192 = 24704 floats (98816 B)
#define LSTM_SMEM_FLOATS 24704
__global__ __launch_bounds__(256) void lstm_step_kernel(int t,
                                                        const float* __restrict__ Whh0,
                                                        const float* __restrict__ Wih1,
                                                        const float* __restrict__ Whh1) {
    extern __shared__ float sm[];
    const int tid = threadIdx.x;
    const int jj = tid & 31;
    const int bg = tid >> 5;  // warp id 0..7

    if (blockIdx.x < 64) {
        // ---- layer0, step t ----
        if (t > 30) return;
        const int b0 = (blockIdx.x >> 2) * 64;
        const int j0 = (blockIdx.x & 3) * 32;
        float* Wp = sm;                 // 64*258
        float* hs = sm + 16512;         // [64][128]
        const float* __restrict__ hprev = g_H0[(t + 1) & 1];
        for (int idx = tid; idx < 2048; idx += 256)
            ((float4*)hs)[idx] = *(const float4*)(hprev + b0 * 128 + idx * 4);
        for (int idx = tid; idx < 128 * 128; idx += 256) {
            int k = idx & 127, r = idx >> 7;
            int q = r >> 5, j = r & 31;
            Wp[(k >> 1) * 258 + r * 2 + (k & 1)] = Whh0[(q * 128 + j0 + j) * 128 + k];
        }
        __syncthreads();
        ull acc[8][4];
#pragma unroll
        for (int i = 0; i < 8; i++)
#pragma unroll
            for (int q = 0; q < 4; q++) acc[i][q] = 0ull;
#pragma unroll 2
        for (int kp = 0; kp < 64; kp++) {
            const float* wrow = Wp + kp * 258 + jj * 2;
            const ull w0 = *(const ull*)(wrow);
            const ull w1v = *(const ull*)(wrow + 64);
            const ull w2 = *(const ull*)(wrow + 128);
            const ull w3 = *(const ull*)(wrow + 192);
#pragma unroll
            for (int i = 0; i < 8; i++) {
                const ull h = *(const ull*)(hs + (bg * 8 + i) * 128 + kp * 2);
                ffma2(acc[i][0], h, w0);
                ffma2(acc[i][1], h, w1v);
                ffma2(acc[i][2], h, w2);
                ffma2(acc[i][3], h, w3);
            }
        }
        const int j = j0 + jj;
#pragma unroll
        for (int i = 0; i < 8; i++) {
            int b = b0 + bg * 8 + i;
            const float* xg = g_xg0 + (b * NP + t) * 512;
            float2 s0 = unpack2(acc[i][0]);
            float2 s1 = unpack2(acc[i][1]);
            float2 s2 = unpack2(acc[i][2]);
            float2 s3 = unpack2(acc[i][3]);
            float gi = s0.x + s0.y + xg[j];
            float gf = s1.x + s1.y + xg[128 + j];
            float gg = s2.x + s2.y + xg[256 + j];
            float go = s3.x + s3.y + xg[384 + j];
            float c = g_C0[b * 128 + j];
            c = sigm(gf) * c + sigm(gi) * tanhf(gg);
            float h = sigm(go) * tanhf(c);
            g_C0[b * 128 + j] = c;
            g_H0[t & 1][b * 128 + j] = h;
        }
    } else {
        // ---- layer1, step s = t-1 ----
        const int s = t - 1;
        if (s < 0) return;
        const int blk = blockIdx.x - 64;    // 0..127
        const int b0 = (blk >> 2) * 32;
        const int j0 = (blk & 3) * 32;
        float* Wp  = sm;
        float* h0s = sm + 16512;            // [32][128]
        float* h1s = h0s + 4096;            // [32][128]
        const float* __restrict__ h0in = g_H0[s & 1];
        const float* __restrict__ h1in = g_H1[(s & 1) ^ 1];
        for (int idx = tid; idx < 1024; idx += 256) {
            ((float4*)h0s)[idx] = *(const float4*)(h0in + b0 * 128 + idx * 4);
            ((float4*)h1s)[idx] = *(const float4*)(h1in + b0 * 128 + idx * 4);
        }
        for (int idx = tid; idx < 128 * 128; idx += 256) {
            int k = idx & 127, r = idx >> 7;
            int q = r >> 5, j = r & 31;
            Wp[(k >> 1) * 258 + r * 2 + (k & 1)] = Wih1[(q * 128 + j0 + j) * 128 + k];
        }
        __syncthreads();
        ull acc[4][4];
#pragma unroll
        for (int i = 0; i < 4; i++)
#pragma unroll
            for (int q = 0; q < 4; q++) acc[i][q] = 0ull;
#pragma unroll 2
        for (int kp = 0; kp < 64; kp++) {
            const float* wrow = Wp + kp * 258 + jj * 2;
            const ull w0 = *(const ull*)(wrow);
            const ull w1v = *(const ull*)(wrow + 64);
            const ull w2 = *(const ull*)(wrow + 128);
            const ull w3 = *(const ull*)(wrow + 192);
#pragma unroll
            for (int i = 0; i < 4; i++) {
                const ull h = *(const ull*)(h0s + (bg * 4 + i) * 128 + kp * 2);
                ffma2(acc[i][0], h, w0);
                ffma2(acc[i][1], h, w1v);
                ffma2(acc[i][2], h, w2);
                ffma2(acc[i][3], h, w3);
            }
        }
        __syncthreads();
        for (int idx = tid; idx < 128 * 128; idx += 256) {
            int k = idx & 127, r = idx >> 7;
            int q = r >> 5, j = r & 31;
            Wp[(k >> 1) * 258 + r * 2 + (k & 1)] = Whh1[(q * 128 + j0 + j) * 128 + k];
        }
        __syncthreads();
#pragma unroll 2
        for (int kp = 0; kp < 64; kp++) {
            const float* wrow = Wp + kp * 258 + jj * 2;
            const ull w0 = *(const ull*)(wrow);
            const ull w1v = *(const ull*)(wrow + 64);
            const ull w2 = *(const ull*)(wrow + 128);
            const ull w3 = *(const ull*)(wrow + 192);
#pragma unroll
            for (int i = 0; i < 4; i++) {
                const ull h = *(const ull*)(h1s + (bg * 4 + i) * 128 + kp * 2);
                ffma2(acc[i][0], h, w0);
                ffma2(acc[i][1], h, w1v);
                ffma2(acc[i][2], h, w2);
                ffma2(acc[i][3], h, w3);
            }
        }
        const int j = j0 + jj;
#pragma unroll
        for (int i = 0; i < 4; i++) {
            int b = b0 + bg * 4 + i;
            float2 s0 = unpack2(acc[i][0]);
            float2 s1 = unpack2(acc[i][1]);
            float2 s2 = unpack2(acc[i][2]);
            float2 s3 = unpack2(acc[i][3]);
            float gi = s0.x + s0.y + g_b1l[j];
            float gf = s1.x + s1.y + g_b1l[128 + j];
            float gg = s2.x + s2.y + g_b1l[256 + j];
            float go = s3.x + s3.y + g_b1l[384 + j];
            float c = g_C1[b * 128 + j];
            c = sigm(gf) * c + sigm(gi) * tanhf(gg);
            float h = sigm(go) * tanhf(c);
            g_C1[b * 128 + j] = c;
            g_H1[s & 1][b * 128 + j] = h;
        }
    }
}

// ---------------- classifier ----------------
__global__ __launch_bounds__(256) void fc1_kernel(const float* __restrict__ bc1) {
    __shared__ float w[128 * 64];
    __shared__ float hsm[4 * 128];
    __shared__ float bsm[64];
    const int tid = threadIdx.x;
    const int b0 = blockIdx.x * 4;
    for (int idx = tid; idx < 8192; idx += 256) w[idx] = g_Wc1t[idx];
    if (tid < 64) bsm[tid] = bc1[tid];
    for (int idx = tid; idx < 512; idx += 256) hsm[idx] = g_H1[0][b0 * 128 + idx];
    __syncthreads();
    const int o = tid & 63, bb = tid >> 6;
    float s = bsm[o];
#pragma unroll 8
    for (int k = 0; k < 128; k++) s += hsm[bb * 128 + k] * w[k * 64 + o];
    g_hid[(b0 + bb) * 64 + o] = fmaxf(s, 0.0f);
}

__global__ __launch_bounds__(256) void fc2_kernel(const float* __restrict__ Wc2,
                                                  const float* __restrict__ bc2,
                                                  float* __restrict__ out) {
    __shared__ float w[11 * 64];
    __shared__ float bsm[11];
    __shared__ float hs[16 * 64];
    const int tid = threadIdx.x;
    const int b0 = blockIdx.x * 16;
    for (int idx = tid; idx < 704; idx += 256) w[idx] = Wc2[idx];
    if (tid < 11) bsm[tid] = bc2[tid];
    for (int idx = tid; idx < 1024; idx += 256) hs[idx] = g_hid[b0 * 64 + idx];
    __syncthreads();
    if (tid < 176) {
        int bb = tid / 11, c = tid - bb * 11;
        float s = bsm[c];
#pragma unroll 8
        for (int k = 0; k < 64; k++) s += hs[bb * 64 + k] * w[c * 64 + k];
        out[(b0 + bb) * 11 + c] = s;
    }
}

// ---------------- launch ----------------
extern "C" void kernel_launch(void* const* d_in, const int* in_sizes, int n_in,
                              void* d_out, int out_size) {
    const float* I    = (const float*)d_in[0];
    const float* Q    = (const float*)d_in[1];
    const float* E    = (const float*)d_in[2];
    const float* Wn1  = (const float*)d_in[3];
    const float* bn1  = (const float*)d_in[4];
    const float* Ws1  = (const float*)d_in[5];
    const float* bs1  = (const float*)d_in[6];
    const float* Wn2  = (const float*)d_in[7];
    const float* bn2  = (const float*)d_in[8];
    const float* Ws2  = (const float*)d_in[9];
    const float* bs2  = (const float*)d_in[10];
    const float* Wih0 = (const float*)d_in[11];
    const float* Whh0 = (const float*)d_in[12];
    const float* bih0 = (const float*)d_in[13];
    const float* bhh0 = (const float*)d_in[14];
    const float* Wih1 = (const float*)d_in[15];
    const float* Whh1 = (const float*)d_in[16];
    const float* bih1 = (const float*)d_in[17];
    const float* bhh1 = (const float*)d_in[18];
    const float* Wc1  = (const float*)d_in[19];
    const float* bc1  = (const float*)d_in[20];
    const float* Wc2  = (const float*)d_in[21];
    const float* bc2  = (const float*)d_in[22];
    float* out = (float*)d_out;

    const size_t gnn_smem  = GNN_SMEM_FLOATS * sizeof(float);   // 76800 B
    const size_t lstm_smem = LSTM_SMEM_FLOATS * sizeof(float);  // 98816 B
    cudaFuncSetAttribute(gnn_kernel, cudaFuncAttributeMaxDynamicSharedMemorySize, (int)gnn_smem);
    cudaFuncSetAttribute(lstm_step_kernel, cudaFuncAttributeMaxDynamicSharedMemorySize, (int)lstm_smem);

    prep_kernel<<<1, 256>>>(E, Wn1, bn1, Ws1, bs1, Wn2, bn2, Ws2, bs2,
                            Wih0, bih0, bhh0, bih1, bhh1, Wc1);
    zero_kernel<<<512, 256>>>();
    gnn_kernel<<<(NBATCH * NP) / 2, 256, gnn_smem>>>(I, Q);
    xg0_kernel<<<dim3((NBATCH * NP) / 64, 8), 256>>>();
    for (int t = 0; t < 32; t++)
        lstm_step_kernel<<<192, 256, lstm_smem>>>(t, Whh0, Wih1, Whh1);
    fc1_kernel<<<NBATCH / 4, 256>>>(bc1);
    fc2_kernel<<<NBATCH / 16, 256>>>(Wc2, bc2, out);
    (void)in_sizes; (void)n_in; (void)out_size;
}

// round 9
// speedup vs baseline: 1.2923x; 1.0047x over previous
#include <cuda_runtime.h>
#include <math.h>

// ---------------- problem constants ----------------
#define NBATCH 1024
#define NP     31
#define RHD    128
#define NC     11

typedef unsigned long long ull;

// ---------------- f32x2 packed-FMA helpers ----------------
__device__ __forceinline__ void ffma2(ull& d, ull a, ull b) {
    asm("fma.rn.f32x2 %0, %1, %2, %0;" : "+l"(d) : "l"(a), "l"(b));
}
__device__ __forceinline__ float2 unpack2(ull v) {
    float2 r; asm("mov.b64 {%0,%1}, %2;" : "=f"(r.x), "=f"(r.y) : "l"(v)); return r;
}
__device__ __forceinline__ float sigm(float x) { return 1.0f / (1.0f + expf(-x)); }

// ---------------- device scratch ----------------
__device__ float g_awT[17 * 64];          // [k][i] banded adj * deg_inv (scalar)
__device__ float g_awT2[17 * 64 * 2];     // [k][i] duplicated pairs (ull view)
__device__ float g_b1[64];
__device__ float g_b2[64];
__device__ float g_w1[256];               // [Ws1t(2x64) ; Wn1t(2x64)]
__device__ float g_Ws2p[4096];            // packed: [dp][o*2+par], par = d&1
__device__ float g_Wn2p[4096];
__device__ float g_b0c[512];
__device__ float g_b1l[512];
__device__ float g_Wih0t[64 * 512];       // [k][n]
__device__ float g_Wc1t[128 * 64];        // [k][o]
__device__ float g_feats[NBATCH * NP * 64];
__device__ float g_xg0[NBATCH * NP * 512];
__device__ float g_H0[2][NBATCH * RHD];
__device__ float g_C0[NBATCH * RHD];
__device__ float g_H1[2][NBATCH * RHD];
__device__ float g_C1[NBATCH * RHD];
__device__ float g_hid[NBATCH * 64];

// ---------------- prep (small, single block) ----------------
__global__ void prep_kernel(const float* __restrict__ E,
                            const float* __restrict__ Wn1, const float* __restrict__ bn1,
                            const float* __restrict__ Ws1, const float* __restrict__ bs1,
                            const float* __restrict__ Wn2, const float* __restrict__ bn2,
                            const float* __restrict__ Ws2, const float* __restrict__ bs2,
                            const float* __restrict__ bih0, const float* __restrict__ bhh0,
                            const float* __restrict__ bih1, const float* __restrict__ bhh1) {
    const int tid = threadIdx.x;
    if (tid < 64) {
        float row[17];
        float deg = 0.0f;
#pragma unroll
        for (int k = 0; k < 17; k++) {
            int j = tid - 8 + k;
            float a = 0.0f;
            if (j >= 0 && j < 64 && j != tid) a = 1.0f / (1.0f + expf(-E[tid * 64 + j]));
            row[k] = a;
            deg += a;
        }
        float inv = deg > 0.0f ? 1.0f / deg : 0.0f;
#pragma unroll
        for (int k = 0; k < 17; k++) g_awT[k * 64 + tid] = row[k] * inv;
        g_b1[tid] = bs1[tid] + bn1[tid];
        g_b2[tid] = bs2[tid] + bn2[tid];
        g_w1[tid]       = Ws1[tid * 2 + 0];
        g_w1[64 + tid]  = Ws1[tid * 2 + 1];
        g_w1[128 + tid] = Wn1[tid * 2 + 0];
        g_w1[192 + tid] = Wn1[tid * 2 + 1];
    }
    __syncthreads();
    for (int idx = tid; idx < 17 * 64; idx += 256) {
        float v = g_awT[idx];
        g_awT2[idx * 2 + 0] = v;
        g_awT2[idx * 2 + 1] = v;
    }
    // packed SAGE2 weights: g_*p[dp*128 + o*2 + par] = W[o][2dp+par]
    for (int idx = tid; idx < 4096; idx += 256) {
        int dp = idx >> 7, rem = idx & 127;
        int o = rem >> 1, par = rem & 1;
        g_Ws2p[idx] = Ws2[o * 64 + 2 * dp + par];
        g_Wn2p[idx] = Wn2[o * 64 + 2 * dp + par];
    }
    for (int idx = tid; idx < 512; idx += 256) {
        g_b0c[idx] = bih0[idx] + bhh0[idx];
        g_b1l[idx] = bih1[idx] + bhh1[idx];
    }
}

// ---------------- prep (big transposes, multi-block) ----------------
__global__ void prep_big_kernel(const float* __restrict__ Wih0,
                                const float* __restrict__ Wc1) {
    int idx = blockIdx.x * blockDim.x + threadIdx.x;
    if (idx < 512 * 64) {
        int n = idx >> 6, k = idx & 63;
        g_Wih0t[k * 512 + n] = Wih0[idx];
    }
    if (idx < 64 * 128) {
        int o = idx >> 7, k = idx & 127;
        g_Wc1t[k * 64 + o] = Wc1[idx];
    }
}

__global__ void zero_kernel() {
    int i = blockIdx.x * blockDim.x + threadIdx.x;
    if (i < NBATCH * RHD) {
        g_H0[1][i] = 0.0f;
        g_C0[i]    = 0.0f;
        g_H1[1][i] = 0.0f;
        g_C1[i]    = 0.0f;
    }
}

// ---------------- fused GNN: 2 patches per CTA, joint GEMM ----------------
// smem layout (float offsets):
//   x1a @0      [4096]
//   n1a @4096   [4096]
//   x1b @8192   [4096]
//   n1b @12288  [4096]
//   Wsp @16384  [4096]
//   Wnp @20480  [4096]
//   awT2@24576  [2176]
//   x0  @26752  [128]
//   n0  @26880  [128]
//   w1  @27008  [256]
//   b1s @27264  [64]
//   b2s @27328  [64]
//   total 27392 floats = 109568 bytes
#define GNN_SMEM_FLOATS 27392
__global__ __launch_bounds__(256, 1) void gnn_kernel(const float* __restrict__ I,
                                                     const float* __restrict__ Q) {
    extern __shared__ float sm[];
    float* const x1a  = sm;
    float* const n1a  = sm + 4096;
    float* const x1b  = sm + 8192;
    float* const n1b  = sm + 12288;
    float* const Wsp  = sm + 16384;
    float* const Wnp  = sm + 20480;
    float* const awT2 = sm + 24576;
    float* const x0   = sm + 26752;
    float* const n0   = sm + 26880;
    float* const w1   = sm + 27008;
    float* const b1s  = sm + 27264;
    float* const b2s  = sm + 27328;

    const int tid = threadIdx.x;

    for (int idx = tid; idx < 1024; idx += 256) {
        ((float4*)Wsp)[idx] = ((const float4*)g_Ws2p)[idx];
        ((float4*)Wnp)[idx] = ((const float4*)g_Wn2p)[idx];
    }
    for (int idx = tid; idx < 2176; idx += 256) awT2[idx] = g_awT2[idx];
    w1[tid] = g_w1[tid];
    if (tid < 64) {
        b1s[tid] = g_b1[tid];
        b2s[tid] = g_b2[tid];
    }

    const int gp0 = blockIdx.x * 2;

    // ---- per-patch phases: x0 -> neigh0 -> sage1 -> conv ----
#pragma unroll 1
    for (int pp = 0; pp < 2; pp++) {
        const int gp = gp0 + pp;
        const int b  = gp / NP;
        const int p  = gp - b * NP;
        float* x1 = pp ? x1b : x1a;
        float* n1 = pp ? n1b : n1a;
        __syncthreads();
        if (tid < 64) {
            int pos = b * 1024 + p * 32 + tid;
            x0[tid * 2 + 0] = I[pos];
            x0[tid * 2 + 1] = Q[pos];
        }
        __syncthreads();

        // neigh0[i][dd] (dd=2)
        if (tid < 128) {
            int i = tid >> 1, dd = tid & 1;
            float s = 0.0f;
#pragma unroll
            for (int k = 0; k < 17; k++) {
                int j = i - 8 + k;
                j = max(0, min(63, j));
                s += awT2[(k * 64 + i) * 2] * x0[j * 2 + dd];
            }
            n0[tid] = s;
        }
        __syncthreads();

        // SAGE layer 1
        {
            const int o = tid & 63, ig = tid >> 6;
            const float ws0 = w1[o], ws1 = w1[64 + o], wn0 = w1[128 + o], wn1 = w1[192 + o];
            const float bb = b1s[o];
#pragma unroll
            for (int ii = 0; ii < 16; ii++) {
                int i = ig * 16 + ii;
                float v = bb + x0[i * 2] * ws0 + x0[i * 2 + 1] * ws1
                             + n0[i * 2] * wn0 + n0[i * 2 + 1] * wn1;
                x1[i * 64 + o] = fmaxf(v, 0.0f);
            }
        }
        __syncthreads();

        // banded conv -> n1: f32x2 over d-pairs with sliding register window over i
        {
            const int dp = tid & 31;
            const int ig = tid >> 5;     // 0..7
            const int i0 = ig * 8;
            ull xw[24];
#pragma unroll
            for (int w = 0; w < 24; w++) {
                int j = i0 - 8 + w;
                j = max(0, min(63, j));
                xw[w] = *(const ull*)(x1 + j * 64 + 2 * dp);
            }
            ull acc[8];
#pragma unroll
            for (int ii = 0; ii < 8; ii++) acc[ii] = 0ull;
#pragma unroll
            for (int k = 0; k < 17; k++) {
#pragma unroll
                for (int ii = 0; ii < 8; ii += 2) {
                    const ulonglong2 aw = *(const ulonglong2*)(awT2 + (k * 64 + i0 + ii) * 2);
                    ffma2(acc[ii],     aw.x, xw[ii + k]);
                    ffma2(acc[ii + 1], aw.y, xw[ii + 1 + k]);
                }
            }
#pragma unroll
            for (int ii = 0; ii < 8; ii++)
                *(ull*)(n1 + (i0 + ii) * 64 + 2 * dp) = acc[ii];
        }
    }
    __syncthreads();

    // ---- joint SAGE2 GEMM over both patches (shared weight loads) ----
    {
        const int ol = tid & 15;            // o = ol + 16c
        const int ig = tid >> 4;            // 0..15
        const int i0 = ig * 4;
        ull accA[4][4], accB[4][4];
#pragma unroll
        for (int ii = 0; ii < 4; ii++)
#pragma unroll
            for (int c = 0; c < 4; c++) { accA[ii][c] = 0ull; accB[ii][c] = 0ull; }

#pragma unroll 1
        for (int dp = 0; dp < 32; dp += 2) {
#pragma unroll
            for (int h = 0; h < 2; h++) {
                ull ws0[2], wn0[2], ws1[2], wn1[2];
#pragma unroll
                for (int cc = 0; cc < 2; cc++) {
                    const int oo = (ol + 16 * (2 * h + cc)) * 2;
                    ws0[cc] = *(const ull*)(Wsp + dp * 128 + oo);
                    wn0[cc] = *(const ull*)(Wnp + dp * 128 + oo);
                    ws1[cc] = *(const ull*)(Wsp + (dp + 1) * 128 + oo);
                    wn1[cc] = *(const ull*)(Wnp + (dp + 1) * 128 + oo);
                }
#pragma unroll
                for (int ii = 0; ii < 4; ii++) {
                    const ulonglong2 aA = *(const ulonglong2*)(x1a + (i0 + ii) * 64 + 2 * dp);
                    const ulonglong2 eA = *(const ulonglong2*)(n1a + (i0 + ii) * 64 + 2 * dp);
#pragma unroll
                    for (int cc = 0; cc < 2; cc++) {
                        ffma2(accA[ii][2 * h + cc], aA.x, ws0[cc]);
                        ffma2(accA[ii][2 * h + cc], eA.x, wn0[cc]);
                        ffma2(accA[ii][2 * h + cc], aA.y, ws1[cc]);
                        ffma2(accA[ii][2 * h + cc], eA.y, wn1[cc]);
                    }
                    const ulonglong2 aB = *(const ulonglong2*)(x1b + (i0 + ii) * 64 + 2 * dp);
                    const ulonglong2 eB = *(const ulonglong2*)(n1b + (i0 + ii) * 64 + 2 * dp);
#pragma unroll
                    for (int cc = 0; cc < 2; cc++) {
                        ffma2(accB[ii][2 * h + cc], aB.x, ws0[cc]);
                        ffma2(accB[ii][2 * h + cc], eB.x, wn0[cc]);
                        ffma2(accB[ii][2 * h + cc], aB.y, ws1[cc]);
                        ffma2(accB[ii][2 * h + cc], eB.y, wn1[cc]);
                    }
                }
            }
        }

        float fsA[4], fsB[4];
#pragma unroll
        for (int c = 0; c < 4; c++) {
            const float bb = b2s[ol + 16 * c];
            float sA = 0.0f, sB = 0.0f;
#pragma unroll
            for (int ii = 0; ii < 4; ii++) {
                float2 vA = unpack2(accA[ii][c]);
                float2 vB = unpack2(accB[ii][c]);
                sA += fmaxf(vA.x + vA.y + bb, 0.0f);
                sB += fmaxf(vB.x + vB.y + bb, 0.0f);
            }
            fsA[c] = sA; fsB[c] = sB;
        }
        __syncthreads();   // done reading x1a/x1b — reuse as reduction buffers
#pragma unroll
        for (int c = 0; c < 4; c++) {
            x1a[ig * 64 + ol + 16 * c] = fsA[c];
            x1b[ig * 64 + ol + 16 * c] = fsB[c];
        }
    }
    __syncthreads();
    if (tid < 64) {
        float s = 0.0f;
#pragma unroll
        for (int g = 0; g < 16; g++) s += x1a[g * 64 + tid];
        g_feats[gp0 * 64 + tid] = s;
    } else if (tid < 128) {
        const int o = tid - 64;
        float s = 0.0f;
#pragma unroll
        for (int g = 0; g < 16; g++) s += x1b[g * 64 + o];
        g_feats[(gp0 + 1) * 64 + o] = s;
    }
}

// ---------------- xg0 = feats @ Wih0^T + bias : [31744 x 512], K=64 ----------------
__global__ __launch_bounds__(256) void xg0_kernel() {
    __shared__ float As[64 * 64];
    __shared__ float Bs[64 * 64];
    __shared__ float bsm[64];
    const int m0 = blockIdx.x * 64;
    const int n0 = blockIdx.y * 64;
    const int tid = threadIdx.x;
    for (int idx = tid; idx < 1024; idx += 256)
        ((float4*)As)[idx] = *(const float4*)(g_feats + (m0 + (idx >> 4)) * 64 + (idx & 15) * 4);
    for (int idx = tid; idx < 1024; idx += 256)
        ((float4*)Bs)[idx] = *(const float4*)(g_Wih0t + (idx >> 4) * 512 + n0 + (idx & 15) * 4);
    if (tid < 64) bsm[tid] = g_b0c[n0 + tid];
    __syncthreads();
    const int mi0 = (tid >> 4) * 4;
    const int ni0 = (tid & 15) * 4;
    ull acc[4][2];
#pragma unroll
    for (int ii = 0; ii < 4; ii++) { acc[ii][0] = 0ull; acc[ii][1] = 0ull; }
#pragma unroll 2
    for (int k = 0; k < 64; k += 4) {
        ulonglong2 bv[4];
#pragma unroll
        for (int kk = 0; kk < 4; kk++) bv[kk] = *(const ulonglong2*)(Bs + (k + kk) * 64 + ni0);
#pragma unroll
        for (int ii = 0; ii < 4; ii++) {
            const float4 a = *(const float4*)(As + (mi0 + ii) * 64 + k);
            ull p;
            asm("mov.b64 %0, {%1,%1};" : "=l"(p) : "f"(a.x));
            ffma2(acc[ii][0], p, bv[0].x); ffma2(acc[ii][1], p, bv[0].y);
            asm("mov.b64 %0, {%1,%1};" : "=l"(p) : "f"(a.y));
            ffma2(acc[ii][0], p, bv[1].x); ffma2(acc[ii][1], p, bv[1].y);
            asm("mov.b64 %0, {%1,%1};" : "=l"(p) : "f"(a.z));
            ffma2(acc[ii][0], p, bv[2].x); ffma2(acc[ii][1], p, bv[2].y);
            asm("mov.b64 %0, {%1,%1};" : "=l"(p) : "f"(a.w));
            ffma2(acc[ii][0], p, bv[3].x); ffma2(acc[ii][1], p, bv[3].y);
        }
    }
#pragma unroll
    for (int ii = 0; ii < 4; ii++) {
        float2 v01 = unpack2(acc[ii][0]);
        float2 v23 = unpack2(acc[ii][1]);
        float* dst = g_xg0 + (m0 + mi0 + ii) * 512 + n0 + ni0;
        dst[0] = v01.x + bsm[ni0 + 0];
        dst[1] = v01.y + bsm[ni0 + 1];
        dst[2] = v23.x + bsm[ni0 + 2];
        dst[3] = v23.y + bsm[ni0 + 3];
    }
}

// ---------------- pipelined LSTM step ----------------
// layer0: blocks [0,64)   — b-tile 64, j-tile 32, 8 batches/thread
// layer1: blocks [64,192) — b-tile 32, j-tile 32, 4 batches/thread
#define LSTM_SMEM_FLOATS 24704
__global__ __launch_bounds__(256) void lstm_step_kernel(int t,
                                                        const float* __restrict__ Whh0,
                                                        const float* __restrict__ Wih1,
                                                        const float* __restrict__ Whh1) {
    extern __shared__ float sm[];
    const int tid = threadIdx.x;
    const int jj = tid & 31;
    const int bg = tid >> 5;  // warp id 0..7

    if (blockIdx.x < 64) {
        if (t > 30) return;
        const int b0 = (blockIdx.x >> 2) * 64;
        const int j0 = (blockIdx.x & 3) * 32;
        float* Wp = sm;                 // 64*258
        float* hs = sm + 16512;         // [64][128]
        const float* __restrict__ hprev = g_H0[(t + 1) & 1];
        for (int idx = tid; idx < 2048; idx += 256)
            ((float4*)hs)[idx] = *(const float4*)(hprev + b0 * 128 + idx * 4);
        for (int idx = tid; idx < 128 * 128; idx += 256) {
            int k = idx & 127, r = idx >> 7;
            int q = r >> 5, j = r & 31;
            Wp[(k >> 1) * 258 + r * 2 + (k & 1)] = Whh0[(q * 128 + j0 + j) * 128 + k];
        }
        __syncthreads();
        ull acc[8][4];
#pragma unroll
        for (int i = 0; i < 8; i++)
#pragma unroll
            for (int q = 0; q < 4; q++) acc[i][q] = 0ull;
#pragma unroll 2
        for (int kp = 0; kp < 64; kp++) {
            const float* wrow = Wp + kp * 258 + jj * 2;
            const ull w0 = *(const ull*)(wrow);
            const ull w1v = *(const ull*)(wrow + 64);
            const ull w2 = *(const ull*)(wrow + 128);
            const ull w3 = *(const ull*)(wrow + 192);
#pragma unroll
            for (int i = 0; i < 8; i++) {
                const ull h = *(const ull*)(hs + (bg * 8 + i) * 128 + kp * 2);
                ffma2(acc[i][0], h, w0);
                ffma2(acc[i][1], h, w1v);
                ffma2(acc[i][2], h, w2);
                ffma2(acc[i][3], h, w3);
            }
        }
        const int j = j0 + jj;
#pragma unroll
        for (int i = 0; i < 8; i++) {
            int b = b0 + bg * 8 + i;
            const float* xg = g_xg0 + (b * NP + t) * 512;
            float2 s0 = unpack2(acc[i][0]);
            float2 s1 = unpack2(acc[i][1]);
            float2 s2 = unpack2(acc[i][2]);
            float2 s3 = unpack2(acc[i][3]);
            float gi = s0.x + s0.y + xg[j];
            float gf = s1.x + s1.y + xg[128 + j];
            float gg = s2.x + s2.y + xg[256 + j];
            float go = s3.x + s3.y + xg[384 + j];
            float c = g_C0[b * 128 + j];
            c = sigm(gf) * c + sigm(gi) * tanhf(gg);
            float h = sigm(go) * tanhf(c);
            g_C0[b * 128 + j] = c;
            g_H0[t & 1][b * 128 + j] = h;
        }
    } else {
        const int s = t - 1;
        if (s < 0) return;
        const int blk = blockIdx.x - 64;    // 0..127
        const int b0 = (blk >> 2) * 32;
        const int j0 = (blk & 3) * 32;
        float* Wp  = sm;
        float* h0s = sm + 16512;            // [32][128]
        float* h1s = h0s + 4096;            // [32][128]
        const float* __restrict__ h0in = g_H0[s & 1];
        const float* __restrict__ h1in = g_H1[(s & 1) ^ 1];
        for (int idx = tid; idx < 1024; idx += 256) {
            ((float4*)h0s)[idx] = *(const float4*)(h0in + b0 * 128 + idx * 4);
            ((float4*)h1s)[idx] = *(const float4*)(h1in + b0 * 128 + idx * 4);
        }
        for (int idx = tid; idx < 128 * 128; idx += 256) {
            int k = idx & 127, r = idx >> 7;
            int q = r >> 5, j = r & 31;
            Wp[(k >> 1) * 258 + r * 2 + (k & 1)] = Wih1[(q * 128 + j0 + j) * 128 + k];
        }
        __syncthreads();
        ull acc[4][4];
#pragma unroll
        for (int i = 0; i < 4; i++)
#pragma unroll
            for (int q = 0; q < 4; q++) acc[i][q] = 0ull;
#pragma unroll 2
        for (int kp = 0; kp < 64; kp++) {
            const float* wrow = Wp + kp * 258 + jj * 2;
            const ull w0 = *(const ull*)(wrow);
            const ull w1v = *(const ull*)(wrow + 64);
            const ull w2 = *(const ull*)(wrow + 128);
            const ull w3 = *(const ull*)(wrow + 192);
#pragma unroll
            for (int i = 0; i < 4; i++) {
                const ull h = *(const ull*)(h0s + (bg * 4 + i) * 128 + kp * 2);
                ffma2(acc[i][0], h, w0);
                ffma2(acc[i][1], h, w1v);
                ffma2(acc[i][2], h, w2);
                ffma2(acc[i][3], h, w3);
            }
        }
        __syncthreads();
        for (int idx = tid; idx < 128 * 128; idx += 256) {
            int k = idx & 127, r = idx >> 7;
            int q = r >> 5, j = r & 31;
            Wp[(k >> 1) * 258 + r * 2 + (k & 1)] = Whh1[(q * 128 + j0 + j) * 128 + k];
        }
        __syncthreads();
#pragma unroll 2
        for (int kp = 0; kp < 64; kp++) {
            const float* wrow = Wp + kp * 258 + jj * 2;
            const ull w0 = *(const ull*)(wrow);
            const ull w1v = *(const ull*)(wrow + 64);
            const ull w2 = *(const ull*)(wrow + 128);
            const ull w3 = *(const ull*)(wrow + 192);
#pragma unroll
            for (int i = 0; i < 4; i++) {
                const ull h = *(const ull*)(h1s + (bg * 4 + i) * 128 + kp * 2);
                ffma2(acc[i][0], h, w0);
                ffma2(acc[i][1], h, w1v);
                ffma2(acc[i][2], h, w2);
                ffma2(acc[i][3], h, w3);
            }
        }
        const int j = j0 + jj;
#pragma unroll
        for (int i = 0; i < 4; i++) {
            int b = b0 + bg * 4 + i;
            float2 s0 = unpack2(acc[i][0]);
            float2 s1 = unpack2(acc[i][1]);
            float2 s2 = unpack2(acc[i][2]);
            float2 s3 = unpack2(acc[i][3]);
            float gi = s0.x + s0.y + g_b1l[j];
            float gf = s1.x + s1.y + g_b1l[128 + j];
            float gg = s2.x + s2.y + g_b1l[256 + j];
            float go = s3.x + s3.y + g_b1l[384 + j];
            float c = g_C1[b * 128 + j];
            c = sigm(gf) * c + sigm(gi) * tanhf(gg);
            float h = sigm(go) * tanhf(c);
            g_C1[b * 128 + j] = c;
            g_H1[s & 1][b * 128 + j] = h;
        }
    }
}

// ---------------- classifier ----------------
__global__ __launch_bounds__(256) void fc1_kernel(const float* __restrict__ bc1) {
    __shared__ float w[128 * 64];
    __shared__ float hsm[4 * 128];
    __shared__ float bsm[64];
    const int tid = threadIdx.x;
    const int b0 = blockIdx.x * 4;
    for (int idx = tid; idx < 8192; idx += 256) w[idx] = g_Wc1t[idx];
    if (tid < 64) bsm[tid] = bc1[tid];
    for (int idx = tid; idx < 512; idx += 256) hsm[idx] = g_H1[0][b0 * 128 + idx];
    __syncthreads();
    const int o = tid & 63, bb = tid >> 6;
    float s = bsm[o];
#pragma unroll 8
    for (int k = 0; k < 128; k++) s += hsm[bb * 128 + k] * w[k * 64 + o];
    g_hid[(b0 + bb) * 64 + o] = fmaxf(s, 0.0f);
}

__global__ __launch_bounds__(256) void fc2_kernel(const float* __restrict__ Wc2,
                                                  const float* __restrict__ bc2,
                                                  float* __restrict__ out) {
    __shared__ float w[11 * 64];
    __shared__ float bsm[11];
    __shared__ float hs[16 * 64];
    const int tid = threadIdx.x;
    const int b0 = blockIdx.x * 16;
    for (int idx = tid; idx < 704; idx += 256) w[idx] = Wc2[idx];
    if (tid < 11) bsm[tid] = bc2[tid];
    for (int idx = tid; idx < 1024; idx += 256) hs[idx] = g_hid[b0 * 64 + idx];
    __syncthreads();
    if (tid < 176) {
        int bb = tid / 11, c = tid - bb * 11;
        float s = bsm[c];
#pragma unroll 8
        for (int k = 0; k < 64; k++) s += hs[bb * 64 + k] * w[c * 64 + k];
        out[(b0 + bb) * 11 + c] = s;
    }
}

// ---------------- launch ----------------
extern "C" void kernel_launch(void* const* d_in, const int* in_sizes, int n_in,
                              void* d_out, int out_size) {
    const float* I    = (const float*)d_in[0];
    const float* Q    = (const float*)d_in[1];
    const float* E    = (const float*)d_in[2];
    const float* Wn1  = (const float*)d_in[3];
    const float* bn1  = (const float*)d_in[4];
    const float* Ws1  = (const float*)d_in[5];
    const float* bs1  = (const float*)d_in[6];
    const float* Wn2  = (const float*)d_in[7];
    const float* bn2  = (const float*)d_in[8];
    const float* Ws2  = (const float*)d_in[9];
    const float* bs2  = (const float*)d_in[10];
    const float* Wih0 = (const float*)d_in[11];
    const float* Whh0 = (const float*)d_in[12];
    const float* bih0 = (const float*)d_in[13];
    const float* bhh0 = (const float*)d_in[14];
    const float* Wih1 = (const float*)d_in[15];
    const float* Whh1 = (const float*)d_in[16];
    const float* bih1 = (const float*)d_in[17];
    const float* bhh1 = (const float*)d_in[18];
    const float* Wc1  = (const float*)d_in[19];
    const float* bc1  = (const float*)d_in[20];
    const float* Wc2  = (const float*)d_in[21];
    const float* bc2  = (const float*)d_in[22];
    float* out = (float*)d_out;

    const size_t gnn_smem  = GNN_SMEM_FLOATS * sizeof(float);   // 109568 B
    const size_t lstm_smem = LSTM_SMEM_FLOATS * sizeof(float);  // 98816 B
    cudaFuncSetAttribute(gnn_kernel, cudaFuncAttributeMaxDynamicSharedMemorySize, (int)gnn_smem);
    cudaFuncSetAttribute(lstm_step_kernel, cudaFuncAttributeMaxDynamicSharedMemorySize, (int)lstm_smem);

    // launch order chosen so gnn_kernel lands in the ncu capture slot (4th launch)
    prep_kernel<<<1, 256>>>(E, Wn1, bn1, Ws1, bs1, Wn2, bn2, Ws2, bs2,
                            bih0, bhh0, bih1, bhh1);
    prep_big_kernel<<<128, 256>>>(Wih0, Wc1);
    zero_kernel<<<512, 256>>>();
    gnn_kernel<<<(NBATCH * NP) / 2, 256, gnn_smem>>>(I, Q);
    xg0_kernel<<<dim3((NBATCH * NP) / 64, 8), 256>>>();
    for (int t = 0; t < 32; t++)
        lstm_step_kernel<<<192, 256, lstm_smem>>>(t, Whh0, Wih1, Whh1);
    fc1_kernel<<<NBATCH / 4, 256>>>(bc1);
    fc2_kernel<<<NBATCH / 16, 256>>>(Wc2, bc2, out);
    (void)in_sizes; (void)n_in; (void)out_size;
}